// round 15
// baseline (speedup 1.0000x reference)
#include <cuda_runtime.h>
#include <cuda_fp16.h>
#include <cstdint>

#define BATCH 4
#define H 128
#define W 128
#define HW (H*W)
#define CIN_X 256
#define CSKIP 128
#define CCAT 384
#define NPAIR (CCAT/2)   // 192
#define COUT 128
#define NPAIR2 (COUT/2)  // 64
#define OPAD 32
#define NPIX (BATCH*HW)
#define EPSV 1e-5f
#define ASTR 72          // halves per smem row (144B)

#define NW1 (9*COUT*NPAIR)    // 221184
#define NW2 (9*COUT*NPAIR2)   // 73728
#define NW3 (9*OPAD*NPAIR2)   // 18432
#define NPREP_BLK ((NW1 + NW2 + NW3 + 255)/256)
#define NUPC_BLK  (NPIX/64)   // 1024 blocks, 64 px each

// ---------------- scratch ------------------------------------------------------
__device__ __align__(16) __half   g_cat[(size_t)BATCH*HW*CCAT];     // CH-LAST fp16
__device__ __align__(16) __half2  g_wpT[NW1];                       // conv1 w [tap][oc][pair]
__device__ __align__(16) __half2  g_wp2T[NW2];                      // def w
__device__ __align__(16) __half2  g_wpoT[NW3];                      // off w (padded)
__device__ __align__(16) __half2  g_hraw[(size_t)BATCH*HW*NPAIR2];  // conv1 out, ch-last fp16
__device__ __align__(16) __half2  g_hh[(size_t)BATCH*HW*NPAIR2];    // BN1+ReLU h, ch-last
__device__ float   g_off[BATCH*18*HW];
__device__ float   g_y[(size_t)BATCH*HW*COUT];
__device__ float g_sum1[COUT], g_sq1[COUT], g_sum2[COUT], g_sq2[COUT];

// ---------------- helpers ------------------------------------------------------
__device__ __forceinline__ void ldm_x4(uint32_t& r0, uint32_t& r1, uint32_t& r2,
                                       uint32_t& r3, uint32_t addr) {
    asm volatile("ldmatrix.sync.aligned.m8n8.x4.shared.b16 {%0,%1,%2,%3}, [%4];"
                 : "=r"(r0), "=r"(r1), "=r"(r2), "=r"(r3) : "r"(addr));
}
__device__ __forceinline__ void mma16816(float* c, const uint32_t* a, const uint32_t* b) {
    asm volatile(
        "mma.sync.aligned.m16n8k16.row.col.f32.f16.f16.f32 "
        "{%0,%1,%2,%3}, {%4,%5,%6,%7}, {%8,%9}, {%0,%1,%2,%3};"
        : "+f"(c[0]), "+f"(c[1]), "+f"(c[2]), "+f"(c[3])
        : "r"(a[0]), "r"(a[1]), "r"(a[2]), "r"(a[3]), "r"(b[0]), "r"(b[1]));
}
__device__ __forceinline__ void cp_async16(uint32_t dst, const void* src) {
    asm volatile("cp.async.cg.shared.global [%0], [%1], 16;"
                 :: "r"(dst), "l"(src) : "memory");
}
__device__ __forceinline__ void cp_async16s(uint32_t dst, const void* src, int ssize) {
    asm volatile("cp.async.cg.shared.global [%0], [%1], 16, %2;"
                 :: "r"(dst), "l"(src), "r"(ssize) : "memory");
}
#define CP_COMMIT() asm volatile("cp.async.commit_group;" ::: "memory")
#define CP_WAIT1()  asm volatile("cp.async.wait_group 1;" ::: "memory")
#define CP_WAIT0()  asm volatile("cp.async.wait_group 0;" ::: "memory")

// ---------------- kernel P: fused zero + weight packs + upcat (transposed) ------
// upcat block: 64 pixels x 192 pairs; phase1 coalesced reads -> smem;
// phase2 segment-fast remap -> contiguous 768B global writes per pixel.
#define UP_SEGS 48              // 16B segments per pixel row (768B)
#define UP_ROW  49              // padded segments (784B) for bank rotation
__global__ void k_prep_upcat(const float* __restrict__ cw, const float* __restrict__ dw,
                             const float* __restrict__ ow, const float* __restrict__ x,
                             const float* __restrict__ skip) {
    if (blockIdx.x < NPREP_BLK) {
        int idx = blockIdx.x * 256 + threadIdx.x;
        if (idx < COUT) { g_sum1[idx]=0.f; g_sq1[idx]=0.f; g_sum2[idx]=0.f; g_sq2[idx]=0.f; }
        if (idx < NW1) {
            int p   = idx % NPAIR;
            int oc  = (idx / NPAIR) % COUT;
            int tap = idx / (NPAIR*COUT);
            float w0 = cw[((size_t)oc*CCAT + 2*p    )*9 + tap];
            float w1 = cw[((size_t)oc*CCAT + 2*p + 1)*9 + tap];
            g_wpT[idx] = __floats2half2_rn(w0, w1);
        } else if (idx < NW1 + NW2) {
            int j = idx - NW1;
            int p   = j % NPAIR2;
            int oc  = (j / NPAIR2) % COUT;
            int tap = j / (NPAIR2*COUT);
            float w0 = dw[((size_t)oc*COUT + 2*p    )*9 + tap];
            float w1 = dw[((size_t)oc*COUT + 2*p + 1)*9 + tap];
            g_wp2T[j] = __floats2half2_rn(w0, w1);
        } else if (idx < NW1 + NW2 + NW3) {
            int j = idx - NW1 - NW2;
            int p   = j % NPAIR2;
            int oc  = (j / NPAIR2) % OPAD;
            int tap = j / (NPAIR2*OPAD);
            float w0 = 0.f, w1 = 0.f;
            if (oc < 18) {
                w0 = ow[((size_t)oc*COUT + 2*p    )*9 + tap];
                w1 = ow[((size_t)oc*COUT + 2*p + 1)*9 + tap];
            }
            g_wpoT[j] = __floats2half2_rn(w0, w1);
        }
        return;
    }

    __shared__ __align__(16) uint4 st[64*UP_ROW];
    int tid = threadIdx.x;
    int pix0 = (blockIdx.x - NPREP_BLK) * 64;      // global pixel base (b*HW + y*W + x)
    int b  = pix0 / HW;
    int yx0 = pix0 - b*HW;

    // phase 1: compute, pixel-fast mapping (coalesced planar reads)
    #pragma unroll
    for (int j = 0; j < 12; j++) {
        int idx = tid + j*256;                      // 0..3071
        int px_l = idx & 63;
        int g4   = idx >> 6;                        // 0..47
        int yx = yx0 + px_l;
        int y = yx >> 7, xc = yx & 127;
        int p0 = g4 * 4;
        __half2 res[4];
        if (p0 < CSKIP/2) {
            const float* sp = skip + ((size_t)(b*CSKIP + 2*p0)*HW) + yx;
            #pragma unroll
            for (int k = 0; k < 4; k++) {
                float v0 = sp[(size_t)(2*k  )*HW];
                float v1 = sp[(size_t)(2*k+1)*HW];
                res[k] = __floats2half2_rn(v0, v1);
            }
        } else {
            int ci0 = 2*p0 - CSKIP;
            float fy = (float)y  * (63.0f / 127.0f);
            float fx = (float)xc * (63.0f / 127.0f);
            int y0 = (int)fy, x0 = (int)fx;
            float wy = fy - (float)y0, wx = fx - (float)x0;
            int y1 = min(y0+1, 63), x1 = min(x0+1, 63);
            int i00 = y0*64+x0, i01 = y0*64+x1, i10 = y1*64+x0, i11 = y1*64+x1;
            float w00 = (1.f-wy)*(1.f-wx), w01 = (1.f-wy)*wx;
            float w10 = wy*(1.f-wx), w11 = wy*wx;
            const float* xp = x + (size_t)(b*CIN_X + ci0)*4096;
            #pragma unroll
            for (int k = 0; k < 4; k++) {
                const float* c0p = xp + (size_t)(2*k)*4096;
                const float* c1p = c0p + 4096;
                float v0 = c0p[i00]*w00 + c0p[i01]*w01 + c0p[i10]*w10 + c0p[i11]*w11;
                float v1 = c1p[i00]*w00 + c1p[i01]*w01 + c1p[i10]*w10 + c1p[i11]*w11;
                res[k] = __floats2half2_rn(v0, v1);
            }
        }
        st[px_l*UP_ROW + g4] = *(uint4*)res;
    }
    __syncthreads();

    // phase 2: segment-fast mapping -> contiguous writes
    uint4* gout = (uint4*)(g_cat + (size_t)pix0*CCAT);
    #pragma unroll
    for (int j = 0; j < 12; j++) {
        int idx = tid + j*256;
        int seg  = idx % UP_SEGS;
        int px_l = idx / UP_SEGS;
        gout[px_l*UP_SEGS + seg] = st[px_l*UP_ROW + seg];
    }
}

// ---------------- kernel B: conv1 — depth-3 B ring (R13, unchanged) -------------
#define HROWS1 204
#define HB1 (HROWS1*128)          // 26112
#define C1_SB 18432
#define C1_HALO0 0
#define C1_HALO1 HB1
#define C1_SB0 (2*HB1)            // 52224
#define C1_SS  (2*HB1 + 3*C1_SB)  // 107520
#define CONV1_SMEM (C1_SS + 1024)
__global__ __launch_bounds__(256, 2) void k_conv1_mma() {
    extern __shared__ __align__(16) unsigned char dynsmem[];
    uint32_t smemU = (uint32_t)__cvta_generic_to_shared(dynsmem);
    float* sS = (float*)(dynsmem + C1_SS);
    float* sQ = sS + COUT;

    int tid = threadIdx.x;
    int wid = tid >> 5, lane = tid & 31;
    int tileX = blockIdx.x * 32, tileY = blockIdx.y * 4;
    int b = blockIdx.z;
    int mBase = (wid & 1) * 64;
    int nBase = (wid >> 1) * 32;
    int grp = lane >> 2, tig = lane & 3;

    uint32_t bOff = (uint32_t)(((nBase + (lane & 7) + ((lane >> 4) & 1)*8)*ASTR
                                + ((lane >> 3) & 1)*8) * 2);
    int aseg = lane >> 4;
    int hrow0[4];
    #pragma unroll
    for (int mi = 0; mi < 4; mi++) {
        int px = mBase + mi*16 + (lane & 15);
        hrow0[mi] = ((px >> 5) + 1)*34 + (px & 31) + 1;
    }

    float acc[4][4][4];
    #pragma unroll
    for (int mi=0;mi<4;mi++)
        #pragma unroll
        for (int ni=0;ni<4;ni++)
            #pragma unroll
            for (int r=0;r<4;r++) acc[mi][ni][r]=0.f;

    int ocb = tid >> 3, segb = tid & 7;

    auto haloLoad = [&](int c, uint32_t hB) {
        #pragma unroll
        for (int k = 0; k < 7; k++) {
            int i = tid + k*256;
            if (i < HROWS1*8) {
                int ph = i >> 3, seg = i & 7;
                int hy = ph / 34, hx = ph - hy*34;
                int gy = tileY - 1 + hy, gx = tileX - 1 + hx;
                bool valid = (gy >= 0) && (gy < H) && (gx >= 0) && (gx < W);
                const __half* src = g_cat
                    + ((size_t)(b*HW + (valid ? gy*W + gx : 0)))*CCAT + c*64 + seg*8;
                cp_async16s(hB + (uint32_t)(ph*128 + ((seg ^ (ph & 7))*16)),
                            src, valid ? 16 : 0);
            }
        }
    };
    auto bLoad = [&](int it, uint32_t bB) {
        int chunk = it / 9, tap = it - chunk*9;
        const __half2* bsrc = g_wpT + (size_t)tap*COUT*NPAIR + chunk*32;
        #pragma unroll
        for (int j = 0; j < 4; j++) {
            int oc = ocb + j*32;
            cp_async16(bB + (uint32_t)((oc*ASTR + segb*8) * 2),
                       bsrc + (size_t)oc*NPAIR + segb*4);
        }
    };

    haloLoad(0, smemU + C1_HALO0);
    bLoad(0, smemU + C1_SB0);
    CP_COMMIT();

    int cur = 0;
    for (int it = 0; it < 54; it++) {
        int chunk = it / 9, tap = it - chunk*9;
        int nxt = (cur == 2) ? 0 : cur + 1;
        if (it < 53) {
            bLoad(it + 1, smemU + C1_SB0 + (uint32_t)nxt*C1_SB);
            if (tap == 8) {
                int nchunk = chunk + 1;
                haloLoad(nchunk, smemU + ((nchunk & 1) ? C1_HALO1 : C1_HALO0));
            }
            CP_COMMIT();
            CP_WAIT1();
        } else {
            CP_WAIT0();
        }
        __syncthreads();

        uint32_t hB = smemU + ((chunk & 1) ? C1_HALO1 : C1_HALO0);
        uint32_t bB = smemU + C1_SB0 + (uint32_t)cur*C1_SB + bOff;
        int dtap = (tap/3 - 1)*34 + (tap - (tap/3)*3 - 1);
        int hrow[4];
        #pragma unroll
        for (int mi = 0; mi < 4; mi++) hrow[mi] = hrow0[mi] + dtap;

        #pragma unroll
        for (int ks = 0; ks < 4; ks++) {
            uint32_t af[4][4], bf[4][2];
            #pragma unroll
            for (int mi = 0; mi < 4; mi++) {
                int seg = ks*2 + aseg;
                uint32_t addr = hB + (uint32_t)(hrow[mi]*128
                                 + ((seg ^ (hrow[mi] & 7))*16));
                ldm_x4(af[mi][0], af[mi][1], af[mi][2], af[mi][3], addr);
            }
            ldm_x4(bf[0][0], bf[0][1], bf[1][0], bf[1][1], bB + ks*32);
            ldm_x4(bf[2][0], bf[2][1], bf[3][0], bf[3][1],
                   bB + 16*ASTR*2 + ks*32);
            #pragma unroll
            for (int mi = 0; mi < 4; mi++)
                #pragma unroll
                for (int ni = 0; ni < 4; ni++)
                    mma16816(acc[mi][ni], af[mi], bf[ni]);
        }
        cur = nxt;
    }

    __syncthreads();
    if (tid < COUT) { sS[tid] = 0.f; sQ[tid] = 0.f; }
    __syncthreads();
    #pragma unroll
    for (int ni = 0; ni < 4; ni++) {
        int oc = nBase + ni*8 + tig*2;
        float s0=0.f,q0=0.f,s1=0.f,q1=0.f;
        #pragma unroll
        for (int mi = 0; mi < 4; mi++) {
            int px0 = mBase + mi*16 + grp;
            int px1 = px0 + 8;
            size_t gp0 = ((size_t)b*HW + (tileY + (px0>>5))*W + tileX + (px0&31))*NPAIR2;
            size_t gp1 = ((size_t)b*HW + (tileY + (px1>>5))*W + tileX + (px1&31))*NPAIR2;
            float a0 = acc[mi][ni][0], a1 = acc[mi][ni][1];
            float a2 = acc[mi][ni][2], a3 = acc[mi][ni][3];
            g_hraw[gp0 + (oc>>1)] = __floats2half2_rn(a0, a1);
            g_hraw[gp1 + (oc>>1)] = __floats2half2_rn(a2, a3);
            s0 += a0 + a2; q0 += a0*a0 + a2*a2;
            s1 += a1 + a3; q1 += a1*a1 + a3*a3;
        }
        atomicAdd(&sS[oc], s0);   atomicAdd(&sQ[oc], q0);
        atomicAdd(&sS[oc+1], s1); atomicAdd(&sQ[oc+1], q1);
    }
    __syncthreads();
    if (tid < COUT) {
        atomicAdd(&g_sum1[tid], sS[tid]);
        atomicAdd(&g_sq1[tid], sQ[tid]);
    }
}

// ---------------- kernel D: fused BN1-finalize + BN1+ReLU -------------------------
__global__ void k_bnrelu1(const float* __restrict__ g, const float* __restrict__ bb) {
    __shared__ float sc[COUT], sh[COUT];
    int tid = threadIdx.x;
    if (tid < COUT) {
        float s = g_sum1[tid], q = g_sq1[tid];
        float m = s / (float)NPIX;
        float v = q / (float)NPIX - m*m;
        float scv = g[tid] * rsqrtf(v + EPSV);
        sc[tid] = scv;
        sh[tid] = bb[tid] - m * scv;
    }
    __syncthreads();
    int idx = blockIdx.x * 256 + tid;
    if (idx >= BATCH*HW*16) return;
    uint4 q = ((const uint4*)g_hraw)[idx];
    int p0 = (idx & 15) * 4;
    uint32_t* e = (uint32_t*)&q;
    uint4 o;
    uint32_t* oe = (uint32_t*)&o;
    #pragma unroll
    for (int j = 0; j < 4; j++) {
        float2 f = __half22float2(*(__half2*)&e[j]);
        int c = 2*(p0 + j);
        float r0 = fmaxf(f.x * sc[c]   + sh[c],   0.f);
        float r1 = fmaxf(f.y * sc[c+1] + sh[c+1], 0.f);
        __half2 hv = __floats2half2_rn(r0, r1);
        oe[j] = *(uint32_t*)&hv;
    }
    ((uint4*)g_hh)[idx] = o;
}

// ---------------- kernel E: offset conv — per-chunk halo (R14, unchanged) ---------
#define OC_SB (OPAD*ASTR*2)       // 4608
#define OC_HALO0 0
#define OC_HALO1 HB1
#define OC_SB0 (2*HB1)            // 52224
#define OFFC_SMEM (2*HB1 + 3*OC_SB)  // 66048
__global__ __launch_bounds__(256, 3) void k_offconv_mma(const float* __restrict__ bias) {
    extern __shared__ __align__(16) unsigned char dynsmem[];
    uint32_t smemU = (uint32_t)__cvta_generic_to_shared(dynsmem);

    int tid = threadIdx.x;
    int wid = tid >> 5, lane = tid & 31;
    int tileX = blockIdx.x * 32, tileY = blockIdx.y * 4;
    int b = blockIdx.z;
    int mBase = (wid & 3) * 32;
    int nBase = (wid >> 2) * 16;
    int grp = lane >> 2, tig = lane & 3;

    uint32_t bOff = (uint32_t)(((nBase + (lane & 7) + ((lane >> 4) & 1)*8)*ASTR
                                + ((lane >> 3) & 1)*8) * 2);
    int aseg = lane >> 4;
    int hrow0[2];
    #pragma unroll
    for (int mi = 0; mi < 2; mi++) {
        int px = mBase + mi*16 + (lane & 15);
        hrow0[mi] = ((px >> 5) + 1)*34 + (px & 31) + 1;
    }

    float acc[2][2][4];
    #pragma unroll
    for (int mi=0;mi<2;mi++)
        #pragma unroll
        for (int ni=0;ni<2;ni++)
            #pragma unroll
            for (int r=0;r<4;r++) acc[mi][ni][r]=0.f;

    int ocb = tid >> 3, segb = tid & 7;

    auto haloLoad = [&](int c, uint32_t hB) {
        #pragma unroll
        for (int k = 0; k < 7; k++) {
            int i = tid + k*256;
            if (i < HROWS1*8) {
                int ph = i >> 3, seg = i & 7;
                int hy = ph / 34, hx = ph - hy*34;
                int gy = tileY - 1 + hy, gx = tileX - 1 + hx;
                bool valid = (gy >= 0) && (gy < H) && (gx >= 0) && (gx < W);
                const __half2* src = g_hh
                    + ((size_t)(b*HW + (valid ? gy*W + gx : 0)))*NPAIR2 + c*32 + seg*4;
                cp_async16s(hB + (uint32_t)(ph*128 + ((seg ^ (ph & 7))*16)),
                            src, valid ? 16 : 0);
            }
        }
    };
    auto bLoad = [&](int it, uint32_t bB) {
        int chunk = it / 9, tap = it - chunk*9;
        const __half2* bsrc = g_wpoT + (size_t)tap*OPAD*NPAIR2 + chunk*32;
        cp_async16(bB + (uint32_t)((ocb*ASTR + segb*8) * 2),
                   bsrc + (size_t)ocb*NPAIR2 + segb*4);
    };

    haloLoad(0, smemU + OC_HALO0);
    bLoad(0, smemU + OC_SB0);
    CP_COMMIT();

    int cur = 0;
    for (int it = 0; it < 18; it++) {
        int chunk = it / 9, tap = it - chunk*9;
        int nxt = (cur == 2) ? 0 : cur + 1;
        if (it < 17) {
            bLoad(it + 1, smemU + OC_SB0 + (uint32_t)nxt*OC_SB);
            if (tap == 8) haloLoad(1, smemU + OC_HALO1);
            CP_COMMIT();
            CP_WAIT1();
        } else {
            CP_WAIT0();
        }
        __syncthreads();

        uint32_t hB = smemU + ((chunk & 1) ? OC_HALO1 : OC_HALO0);
        uint32_t bB = smemU + OC_SB0 + (uint32_t)cur*OC_SB + bOff;
        int dtap = (tap/3 - 1)*34 + (tap - (tap/3)*3 - 1);
        int hrow[2];
        #pragma unroll
        for (int mi = 0; mi < 2; mi++) hrow[mi] = hrow0[mi] + dtap;

        #pragma unroll
        for (int ks = 0; ks < 4; ks++) {
            uint32_t af[2][4], bf[2][2];
            #pragma unroll
            for (int mi = 0; mi < 2; mi++) {
                int seg = ks*2 + aseg;
                uint32_t addr = hB + (uint32_t)(hrow[mi]*128
                                 + ((seg ^ (hrow[mi] & 7))*16));
                ldm_x4(af[mi][0], af[mi][1], af[mi][2], af[mi][3], addr);
            }
            ldm_x4(bf[0][0], bf[0][1], bf[1][0], bf[1][1], bB + ks*32);
            #pragma unroll
            for (int mi = 0; mi < 2; mi++)
                #pragma unroll
                for (int ni = 0; ni < 2; ni++)
                    mma16816(acc[mi][ni], af[mi], bf[ni]);
        }
        cur = nxt;
    }

    #pragma unroll
    for (int ni = 0; ni < 2; ni++) {
        int oc = nBase + ni*8 + tig*2;
        if (oc >= 18) continue;
        float b0 = bias[oc];
        float b1 = (oc + 1 < 18) ? bias[oc+1] : 0.f;
        #pragma unroll
        for (int mi = 0; mi < 2; mi++) {
            int px0 = mBase + mi*16 + grp;
            int px1 = px0 + 8;
            int y0 = tileY + (px0>>5), x0 = tileX + (px0&31);
            int y1 = tileY + (px1>>5), x1 = tileX + (px1&31);
            g_off[((size_t)(b*18 + oc)*HW) + y0*W + x0] = acc[mi][ni][0] + b0;
            g_off[((size_t)(b*18 + oc)*HW) + y1*W + x1] = acc[mi][ni][2] + b0;
            if (oc + 1 < 18) {
                g_off[((size_t)(b*18 + oc + 1)*HW) + y0*W + x0] = acc[mi][ni][1] + b1;
                g_off[((size_t)(b*18 + oc + 1)*HW) + y1*W + x1] = acc[mi][ni][3] + b1;
            }
        }
    }
}

// ---------------- kernel F: deform conv — 2 CTA/SM (unchanged) --------------------
#define D_HALO   0
#define D_SA     36864
#define D_SB     73728
#define D_SS     110592
#define D_SQ     111104
#define DEF_SMEM 111616
__global__ __launch_bounds__(256, 2) void k_deform_mma(const float* __restrict__ db) {
    extern __shared__ __align__(16) unsigned char dyn[];
    const char* halo = (const char*)(dyn + D_HALO);
    float* sS = (float*)(dyn + D_SS);
    float* sQ = (float*)(dyn + D_SQ);
    uint32_t smemU = (uint32_t)__cvta_generic_to_shared(dyn);
    uint32_t haloU = smemU + D_HALO;
    uint32_t sA_u  = smemU + D_SA;
    uint32_t sB_u  = smemU + D_SB;
    __half* sA = (__half*)(dyn + D_SA);

    int tid = threadIdx.x;
    int wid = tid >> 5, lane = tid & 31;
    int tileX = blockIdx.x * 32, tileY = blockIdx.y * 4;
    int b = blockIdx.z;
    int mBase = (wid & 1) * 64;
    int nBase = (wid >> 1) * 32;
    int grp = lane >> 2, tig = lane & 3;
    int hY0 = tileY - 2, hX0 = tileX - 2;

    uint32_t aOff = (uint32_t)(((mBase + (lane & 15))*ASTR + (lane >> 4)*8) * 2);
    uint32_t bOff = (uint32_t)(((nBase + (lane & 7) + ((lane >> 4) & 1)*8)*ASTR
                                + ((lane >> 3) & 1)*8) * 2);

    float acc[4][4][4];
    #pragma unroll
    for (int mi=0;mi<4;mi++)
        #pragma unroll
        for (int ni=0;ni<4;ni++)
            #pragma unroll
            for (int r=0;r<4;r++) acc[mi][ni][r]=0.f;

    int px_s = tid & 127;
    int half_s = tid >> 7;
    int ocb = tid >> 3, segb = tid & 7;
    int py_s = tileY + (px_s >> 5), pxg_s = tileX + (px_s & 31);

    auto haloLoad = [&](int chunk) {
        #pragma unroll
        for (int k = 0; k < 9; k++) {
            int i = tid + k*256;
            int ph = i >> 3, seg = i & 7;
            int yr = min(max(hY0 + ph/36, 0), H-1);
            int xr = min(max(hX0 + ph%36, 0), W-1);
            const __half2* src = g_hh + ((size_t)(b*HW + yr*W + xr))*NPAIR2
                                 + chunk*32 + seg*4;
            cp_async16(haloU + (uint32_t)(ph*128 + ((seg ^ (ph & 7))*16)), src);
        }
    };
    auto bLoad = [&](int it) {
        int chunk = it / 9, tap = it - chunk*9;
        const __half2* bsrc = g_wp2T + (size_t)tap*COUT*NPAIR2 + chunk*32;
        uint32_t bB = sB_u + (uint32_t)(it & 1)*18432;
        #pragma unroll
        for (int j = 0; j < 4; j++) {
            int oc = ocb + j*32;
            cp_async16(bB + (uint32_t)((oc*ASTR + segb*8) * 2),
                       bsrc + (size_t)oc*NPAIR2 + segb*4);
        }
    };

    auto gather = [&](int it, int buf) {
        int chunk = it / 9, tap = it - chunk*9;
        float dy = g_off[((size_t)(b*18 + 2*tap    )*HW) + py_s*W + pxg_s];
        float dx = g_off[((size_t)(b*18 + 2*tap + 1)*HW) + py_s*W + pxg_s];
        float py  = (float)py_s + (float)(tap/3 - 1) + dy;
        float pxx = (float)pxg_s + (float)(tap - (tap/3)*3 - 1) + dx;
        float y0f = floorf(py), x0f = floorf(pxx);
        float wy = py - y0f, wx = pxx - x0f;
        int yi = (int)y0f, xi = (int)x0f;
        bool yv0 = (yi >= 0) && (yi < H);
        bool yv1 = (yi+1 >= 0) && (yi+1 < H);
        bool xv0 = (xi >= 0) && (xi < W);
        bool xv1 = (xi+1 >= 0) && (xi+1 < W);
        float w00 = (yv0 && xv0) ? (1.f-wy)*(1.f-wx) : 0.f;
        float w01 = (yv0 && xv1) ? (1.f-wy)*wx       : 0.f;
        float w10 = (yv1 && xv0) ? wy*(1.f-wx)       : 0.f;
        float w11 = (yv1 && xv1) ? wy*wx             : 0.f;
        int ry0 = min(max(yi,   0), H-1) - hY0;
        int ry1 = min(max(yi+1, 0), H-1) - hY0;
        int rx0 = min(max(xi,   0), W-1) - hX0;
        int rx1 = min(max(xi+1, 0), W-1) - hX0;
        bool inHalo = (ry0 >= 0) && (ry1 < 8) && (rx0 >= 0) && (rx1 < 36);
        int segBase = half_s*4;
        uint32_t res[4][4];
        if (inHalo) {
            int h00 = ry0*36 + rx0, h01 = ry0*36 + rx1;
            int h10 = ry1*36 + rx0, h11 = ry1*36 + rx1;
            #pragma unroll
            for (int j = 0; j < 4; j++) {
                int seg = segBase + j;
                uint4 q0 = *(const uint4*)(halo + h00*128 + ((seg ^ (h00 & 7))*16));
                uint4 q1 = *(const uint4*)(halo + h01*128 + ((seg ^ (h01 & 7))*16));
                uint4 q2 = *(const uint4*)(halo + h10*128 + ((seg ^ (h10 & 7))*16));
                uint4 q3 = *(const uint4*)(halo + h11*128 + ((seg ^ (h11 & 7))*16));
                const uint32_t* a0 = (const uint32_t*)&q0;
                const uint32_t* a1 = (const uint32_t*)&q1;
                const uint32_t* a2 = (const uint32_t*)&q2;
                const uint32_t* a3 = (const uint32_t*)&q3;
                #pragma unroll
                for (int e = 0; e < 4; e++) {
                    float2 f0 = __half22float2(*(__half2*)&a0[e]);
                    float2 f1 = __half22float2(*(__half2*)&a1[e]);
                    float2 f2 = __half22float2(*(__half2*)&a2[e]);
                    float2 f3 = __half22float2(*(__half2*)&a3[e]);
                    float rxv = w00*f0.x + w01*f1.x + w10*f2.x + w11*f3.x;
                    float ryv = w00*f0.y + w01*f1.y + w10*f2.y + w11*f3.y;
                    __half2 hv = __floats2half2_rn(rxv, ryv);
                    res[j][e] = *(uint32_t*)&hv;
                }
            }
        } else {
            int pb = chunk*32 + half_s*16;
            const uint4* p0 = (const uint4*)(g_hh + ((size_t)b*HW + (hY0+ry0)*W + hX0+rx0)*NPAIR2 + pb);
            const uint4* p1 = (const uint4*)(g_hh + ((size_t)b*HW + (hY0+ry0)*W + hX0+rx1)*NPAIR2 + pb);
            const uint4* p2 = (const uint4*)(g_hh + ((size_t)b*HW + (hY0+ry1)*W + hX0+rx0)*NPAIR2 + pb);
            const uint4* p3 = (const uint4*)(g_hh + ((size_t)b*HW + (hY0+ry1)*W + hX0+rx1)*NPAIR2 + pb);
            #pragma unroll
            for (int j = 0; j < 4; j++) {
                uint4 q0 = p0[j], q1 = p1[j], q2 = p2[j], q3 = p3[j];
                const uint32_t* a0 = (const uint32_t*)&q0;
                const uint32_t* a1 = (const uint32_t*)&q1;
                const uint32_t* a2 = (const uint32_t*)&q2;
                const uint32_t* a3 = (const uint32_t*)&q3;
                #pragma unroll
                for (int e = 0; e < 4; e++) {
                    float2 f0 = __half22float2(*(__half2*)&a0[e]);
                    float2 f1 = __half22float2(*(__half2*)&a1[e]);
                    float2 f2 = __half22float2(*(__half2*)&a2[e]);
                    float2 f3 = __half22float2(*(__half2*)&a3[e]);
                    float rxv = w00*f0.x + w01*f1.x + w10*f2.x + w11*f3.x;
                    float ryv = w00*f0.y + w01*f1.y + w10*f2.y + w11*f3.y;
                    __half2 hv = __floats2half2_rn(rxv, ryv);
                    res[j][e] = *(uint32_t*)&hv;
                }
            }
        }
        __half* dst = sA + (size_t)buf*(128*ASTR) + px_s*ASTR + half_s*32;
        #pragma unroll
        for (int j = 0; j < 4; j++)
            *(uint4*)(dst + j*8) = *(uint4*)res[j];
    };

    auto mmaStep = [&](int it) {
        uint32_t aB = sA_u + (uint32_t)(it & 1)*18432 + aOff;
        uint32_t bB = sB_u + (uint32_t)(it & 1)*18432 + bOff;
        #pragma unroll
        for (int ks = 0; ks < 4; ks++) {
            uint32_t af[4][4], bf[4][2];
            #pragma unroll
            for (int mi = 0; mi < 4; mi++)
                ldm_x4(af[mi][0], af[mi][1], af[mi][2], af[mi][3],
                       aB + mi*(16*ASTR*2) + ks*32);
            ldm_x4(bf[0][0], bf[0][1], bf[1][0], bf[1][1], bB + ks*32);
            ldm_x4(bf[2][0], bf[2][1], bf[3][0], bf[3][1],
                   bB + 16*ASTR*2 + ks*32);
            #pragma unroll
            for (int mi = 0; mi < 4; mi++)
                #pragma unroll
                for (int ni = 0; ni < 4; ni++)
                    mma16816(acc[mi][ni], af[mi], bf[ni]);
        }
    };

    haloLoad(0);
    bLoad(0);
    CP_COMMIT();
    CP_WAIT0();
    __syncthreads();
    gather(0, 0);

    for (int it = 0; it < 18; it++) {
        __syncthreads();
        if (it == 8) {
            haloLoad(1);
            bLoad(9);
            CP_COMMIT();
            mmaStep(8);
            CP_WAIT0();
            continue;
        }
        if (it == 9) {
            gather(9, 1);
            bLoad(10);
            CP_COMMIT();
            gather(10, 0);
            CP_WAIT1();
            __syncthreads();
            mmaStep(9);
            continue;
        }
        if (it < 17) {
            bLoad(it+1);
            CP_COMMIT();
            if (it+1 != 9 && it+1 != 10) gather(it+1, (it+1) & 1);
            CP_WAIT1();
        } else {
            CP_WAIT0();
        }
        __syncthreads();
        mmaStep(it);
    }

    __syncthreads();
    if (tid < COUT) { sS[tid] = 0.f; sQ[tid] = 0.f; }
    __syncthreads();
    #pragma unroll
    for (int ni = 0; ni < 4; ni++) {
        int oc = nBase + ni*8 + tig*2;
        float b0 = db[oc], b1 = db[oc+1];
        float s0=0.f,q0=0.f,s1=0.f,q1=0.f;
        #pragma unroll
        for (int mi = 0; mi < 4; mi++) {
            int px0 = mBase + mi*16 + grp;
            int px1 = px0 + 8;
            size_t gp0 = ((size_t)b*HW + (tileY + (px0>>5))*W + tileX + (px0&31))*COUT;
            size_t gp1 = ((size_t)b*HW + (tileY + (px1>>5))*W + tileX + (px1&31))*COUT;
            float a0 = acc[mi][ni][0] + b0, a1 = acc[mi][ni][1] + b1;
            float a2 = acc[mi][ni][2] + b0, a3 = acc[mi][ni][3] + b1;
            *(float2*)&g_y[gp0 + oc] = make_float2(a0, a1);
            *(float2*)&g_y[gp1 + oc] = make_float2(a2, a3);
            s0 += a0 + a2; q0 += a0*a0 + a2*a2;
            s1 += a1 + a3; q1 += a1*a1 + a3*a3;
        }
        atomicAdd(&sS[oc], s0);   atomicAdd(&sQ[oc], q0);
        atomicAdd(&sS[oc+1], s1); atomicAdd(&sQ[oc+1], q1);
    }
    __syncthreads();
    if (tid < COUT) {
        atomicAdd(&g_sum2[tid], sS[tid]);
        atomicAdd(&g_sq2[tid], sQ[tid]);
    }
}

// ---------------- kernel H: fused BN2-finalize + BN2+ReLU -> planar out -----------
__global__ __launch_bounds__(256) void k_bnrelu2(const float* __restrict__ g,
                                                 const float* __restrict__ bb,
                                                 float* __restrict__ out) {
    __shared__ float s[32][129];
    __shared__ float sc[COUT], sh[COUT];
    int tid = threadIdx.x;
    if (tid < COUT) {
        float su = g_sum2[tid], q = g_sq2[tid];
        float m = su / (float)NPIX;
        float v = q / (float)NPIX - m*m;
        float scv = g[tid] * rsqrtf(v + EPSV);
        sc[tid] = scv;
        sh[tid] = bb[tid] - m * scv;
    }
    int px0 = blockIdx.x * 32;
    int b = blockIdx.y;
    #pragma unroll
    for (int j = 0; j < 16; j++) {
        int idx = tid + j*256;
        int pxl = idx >> 7, c = idx & 127;
        s[pxl][c] = g_y[((size_t)b*HW + px0 + pxl)*COUT + c];
    }
    __syncthreads();
    #pragma unroll
    for (int j = 0; j < 16; j++) {
        int idx = tid + j*256;
        int c = idx >> 5, pxl = idx & 31;
        float v = s[pxl][c] * sc[c] + sh[c];
        out[((size_t)(b*COUT + c)*HW) + px0 + pxl] = fmaxf(v, 0.f);
    }
}

// ---------------- launch -----------------------------------------------------------
extern "C" void kernel_launch(void* const* d_in, const int* in_sizes, int n_in,
                              void* d_out, int out_size) {
    const float* x       = (const float*)d_in[0];
    const float* skip    = (const float*)d_in[1];
    const float* conv1_w = (const float*)d_in[2];
    const float* bn1_g   = (const float*)d_in[3];
    const float* bn1_b   = (const float*)d_in[4];
    const float* off_w   = (const float*)d_in[5];
    const float* off_b   = (const float*)d_in[6];
    const float* def_w   = (const float*)d_in[7];
    const float* def_b   = (const float*)d_in[8];
    const float* bn2_g   = (const float*)d_in[9];
    const float* bn2_b   = (const float*)d_in[10];
    float* out = (float*)d_out;

    static bool attrDone = false;
    if (!attrDone) {
        cudaFuncSetAttribute(k_conv1_mma,
                             cudaFuncAttributeMaxDynamicSharedMemorySize, CONV1_SMEM);
        cudaFuncSetAttribute(k_offconv_mma,
                             cudaFuncAttributeMaxDynamicSharedMemorySize, OFFC_SMEM);
        cudaFuncSetAttribute(k_deform_mma,
                             cudaFuncAttributeMaxDynamicSharedMemorySize, DEF_SMEM);
        attrDone = true;
    }

    k_prep_upcat<<<NPREP_BLK + NUPC_BLK, 256>>>(conv1_w, def_w, off_w, x, skip);

    k_conv1_mma<<<dim3(W/32, H/4, BATCH), 256, CONV1_SMEM>>>();

    int nhp = BATCH*HW*16;
    k_bnrelu1<<<(nhp + 255)/256, 256>>>(bn1_g, bn1_b);

    k_offconv_mma<<<dim3(W/32, H/4, BATCH), 256, OFFC_SMEM>>>(off_b);

    k_deform_mma<<<dim3(W/32, H/4, BATCH), 256, DEF_SMEM>>>(def_b);

    k_bnrelu2<<<dim3(HW/32, BATCH), 256>>>(bn2_g, bn2_b, out);
}

// round 16
// speedup vs baseline: 1.0147x; 1.0147x over previous
#include <cuda_runtime.h>
#include <cuda_fp16.h>
#include <cstdint>

#define BATCH 4
#define H 128
#define W 128
#define HW (H*W)
#define CIN_X 256
#define CSKIP 128
#define CCAT 384
#define NPAIR (CCAT/2)   // 192
#define COUT 128
#define NPAIR2 (COUT/2)  // 64
#define OPAD 32
#define NPIX (BATCH*HW)
#define EPSV 1e-5f
#define ASTR 72          // halves per smem row (144B)

#define NW1 (9*COUT*NPAIR)    // 221184
#define NW2 (9*COUT*NPAIR2)   // 73728
#define NW3 (9*OPAD*NPAIR2)   // 18432
#define NPREP_BLK ((NW1 + NW2 + NW3 + 255)/256)
#define NUP_BLK   ((BATCH*HW*(NPAIR/4) + 255)/256)

// ---------------- scratch ------------------------------------------------------
__device__ __align__(16) __half   g_cat[(size_t)BATCH*HW*CCAT];     // CH-LAST fp16
__device__ __align__(16) __half2  g_wpT[NW1];                       // conv1 w [tap][oc][pair]
__device__ __align__(16) __half2  g_wp2T[NW2];                      // def w
__device__ __align__(16) __half2  g_wpoT[NW3];                      // off w (padded)
__device__ __align__(16) __half2  g_hraw[(size_t)BATCH*HW*NPAIR2];  // conv1 out, ch-last fp16
__device__ __align__(16) __half2  g_hh[(size_t)BATCH*HW*NPAIR2];    // BN1+ReLU h, ch-last
__device__ float   g_off[BATCH*18*HW];
__device__ float   g_y[(size_t)BATCH*HW*COUT];
__device__ float g_sum1[COUT], g_sq1[COUT], g_sum2[COUT], g_sq2[COUT];

// ---------------- helpers ------------------------------------------------------
__device__ __forceinline__ void ldm_x4(uint32_t& r0, uint32_t& r1, uint32_t& r2,
                                       uint32_t& r3, uint32_t addr) {
    asm volatile("ldmatrix.sync.aligned.m8n8.x4.shared.b16 {%0,%1,%2,%3}, [%4];"
                 : "=r"(r0), "=r"(r1), "=r"(r2), "=r"(r3) : "r"(addr));
}
__device__ __forceinline__ void mma16816(float* c, const uint32_t* a, const uint32_t* b) {
    asm volatile(
        "mma.sync.aligned.m16n8k16.row.col.f32.f16.f16.f32 "
        "{%0,%1,%2,%3}, {%4,%5,%6,%7}, {%8,%9}, {%0,%1,%2,%3};"
        : "+f"(c[0]), "+f"(c[1]), "+f"(c[2]), "+f"(c[3])
        : "r"(a[0]), "r"(a[1]), "r"(a[2]), "r"(a[3]), "r"(b[0]), "r"(b[1]));
}
__device__ __forceinline__ void cp_async16(uint32_t dst, const void* src) {
    asm volatile("cp.async.cg.shared.global [%0], [%1], 16;"
                 :: "r"(dst), "l"(src) : "memory");
}
__device__ __forceinline__ void cp_async16s(uint32_t dst, const void* src, int ssize) {
    asm volatile("cp.async.cg.shared.global [%0], [%1], 16, %2;"
                 :: "r"(dst), "l"(src), "r"(ssize) : "memory");
}
#define CP_COMMIT() asm volatile("cp.async.commit_group;" ::: "memory")
#define CP_WAIT1()  asm volatile("cp.async.wait_group 1;" ::: "memory")
#define CP_WAIT0()  asm volatile("cp.async.wait_group 0;" ::: "memory")

// ---------------- kernel P: fused zero + weight packs + upcat (R14 version) -----
__global__ void k_prep_upcat(const float* __restrict__ cw, const float* __restrict__ dw,
                             const float* __restrict__ ow, const float* __restrict__ x,
                             const float* __restrict__ skip) {
    if (blockIdx.x < NPREP_BLK) {
        int idx = blockIdx.x * 256 + threadIdx.x;
        if (idx < COUT) { g_sum1[idx]=0.f; g_sq1[idx]=0.f; g_sum2[idx]=0.f; g_sq2[idx]=0.f; }
        if (idx < NW1) {
            int p   = idx % NPAIR;
            int oc  = (idx / NPAIR) % COUT;
            int tap = idx / (NPAIR*COUT);
            float w0 = cw[((size_t)oc*CCAT + 2*p    )*9 + tap];
            float w1 = cw[((size_t)oc*CCAT + 2*p + 1)*9 + tap];
            g_wpT[idx] = __floats2half2_rn(w0, w1);
        } else if (idx < NW1 + NW2) {
            int j = idx - NW1;
            int p   = j % NPAIR2;
            int oc  = (j / NPAIR2) % COUT;
            int tap = j / (NPAIR2*COUT);
            float w0 = dw[((size_t)oc*COUT + 2*p    )*9 + tap];
            float w1 = dw[((size_t)oc*COUT + 2*p + 1)*9 + tap];
            g_wp2T[j] = __floats2half2_rn(w0, w1);
        } else if (idx < NW1 + NW2 + NW3) {
            int j = idx - NW1 - NW2;
            int p   = j % NPAIR2;
            int oc  = (j / NPAIR2) % OPAD;
            int tap = j / (NPAIR2*OPAD);
            float w0 = 0.f, w1 = 0.f;
            if (oc < 18) {
                w0 = ow[((size_t)oc*COUT + 2*p    )*9 + tap];
                w1 = ow[((size_t)oc*COUT + 2*p + 1)*9 + tap];
            }
            g_wpoT[j] = __floats2half2_rn(w0, w1);
        }
        return;
    }
    int idx = (blockIdx.x - NPREP_BLK) * 256 + threadIdx.x;
    if (idx >= BATCH*HW*(NPAIR/4)) return;
    int xc = idx % W;
    int y  = (idx / W) % H;
    int g4 = (idx / HW) % (NPAIR/4);
    int b  = idx / (HW*(NPAIR/4));
    int p0 = g4 * 4;
    __half2 res[4];
    if (p0 < CSKIP/2) {
        const float* sp = skip + ((size_t)(b*CSKIP + 2*p0)*HW) + y*W + xc;
        #pragma unroll
        for (int j = 0; j < 4; j++) {
            float v0 = sp[(size_t)(2*j  )*HW];
            float v1 = sp[(size_t)(2*j+1)*HW];
            res[j] = __floats2half2_rn(v0, v1);
        }
    } else {
        int ci0 = 2*p0 - CSKIP;
        float fy = (float)y  * (63.0f / 127.0f);
        float fx = (float)xc * (63.0f / 127.0f);
        int y0 = (int)fy, x0 = (int)fx;
        float wy = fy - (float)y0, wx = fx - (float)x0;
        int y1 = min(y0+1, 63), x1 = min(x0+1, 63);
        int i00 = y0*64+x0, i01 = y0*64+x1, i10 = y1*64+x0, i11 = y1*64+x1;
        float w00 = (1.f-wy)*(1.f-wx), w01 = (1.f-wy)*wx;
        float w10 = wy*(1.f-wx), w11 = wy*wx;
        const float* xp = x + (size_t)(b*CIN_X + ci0)*4096;
        #pragma unroll
        for (int j = 0; j < 4; j++) {
            const float* c0p = xp + (size_t)(2*j)*4096;
            const float* c1p = c0p + 4096;
            float v0 = c0p[i00]*w00 + c0p[i01]*w01 + c0p[i10]*w10 + c0p[i11]*w11;
            float v1 = c1p[i00]*w00 + c1p[i01]*w01 + c1p[i10]*w10 + c1p[i11]*w11;
            res[j] = __floats2half2_rn(v0, v1);
        }
    }
    *(uint4*)&g_cat[((size_t)(b*HW + y*W + xc))*CCAT + p0*2] = *(uint4*)res;
}

// ---------------- kernel B: conv1 — depth-3 B ring (unchanged) ------------------
#define HROWS1 204
#define HB1 (HROWS1*128)          // 26112
#define C1_SB 18432
#define C1_HALO0 0
#define C1_HALO1 HB1
#define C1_SB0 (2*HB1)            // 52224
#define C1_SS  (2*HB1 + 3*C1_SB)  // 107520
#define CONV1_SMEM (C1_SS + 1024)
__global__ __launch_bounds__(256, 2) void k_conv1_mma() {
    extern __shared__ __align__(16) unsigned char dynsmem[];
    uint32_t smemU = (uint32_t)__cvta_generic_to_shared(dynsmem);
    float* sS = (float*)(dynsmem + C1_SS);
    float* sQ = sS + COUT;

    int tid = threadIdx.x;
    int wid = tid >> 5, lane = tid & 31;
    int tileX = blockIdx.x * 32, tileY = blockIdx.y * 4;
    int b = blockIdx.z;
    int mBase = (wid & 1) * 64;
    int nBase = (wid >> 1) * 32;
    int grp = lane >> 2, tig = lane & 3;

    uint32_t bOff = (uint32_t)(((nBase + (lane & 7) + ((lane >> 4) & 1)*8)*ASTR
                                + ((lane >> 3) & 1)*8) * 2);
    int aseg = lane >> 4;
    int hrow0[4];
    #pragma unroll
    for (int mi = 0; mi < 4; mi++) {
        int px = mBase + mi*16 + (lane & 15);
        hrow0[mi] = ((px >> 5) + 1)*34 + (px & 31) + 1;
    }

    float acc[4][4][4];
    #pragma unroll
    for (int mi=0;mi<4;mi++)
        #pragma unroll
        for (int ni=0;ni<4;ni++)
            #pragma unroll
            for (int r=0;r<4;r++) acc[mi][ni][r]=0.f;

    int ocb = tid >> 3, segb = tid & 7;

    auto haloLoad = [&](int c, uint32_t hB) {
        #pragma unroll
        for (int k = 0; k < 7; k++) {
            int i = tid + k*256;
            if (i < HROWS1*8) {
                int ph = i >> 3, seg = i & 7;
                int hy = ph / 34, hx = ph - hy*34;
                int gy = tileY - 1 + hy, gx = tileX - 1 + hx;
                bool valid = (gy >= 0) && (gy < H) && (gx >= 0) && (gx < W);
                const __half* src = g_cat
                    + ((size_t)(b*HW + (valid ? gy*W + gx : 0)))*CCAT + c*64 + seg*8;
                cp_async16s(hB + (uint32_t)(ph*128 + ((seg ^ (ph & 7))*16)),
                            src, valid ? 16 : 0);
            }
        }
    };
    auto bLoad = [&](int it, uint32_t bB) {
        int chunk = it / 9, tap = it - chunk*9;
        const __half2* bsrc = g_wpT + (size_t)tap*COUT*NPAIR + chunk*32;
        #pragma unroll
        for (int j = 0; j < 4; j++) {
            int oc = ocb + j*32;
            cp_async16(bB + (uint32_t)((oc*ASTR + segb*8) * 2),
                       bsrc + (size_t)oc*NPAIR + segb*4);
        }
    };

    haloLoad(0, smemU + C1_HALO0);
    bLoad(0, smemU + C1_SB0);
    CP_COMMIT();

    int cur = 0;
    for (int it = 0; it < 54; it++) {
        int chunk = it / 9, tap = it - chunk*9;
        int nxt = (cur == 2) ? 0 : cur + 1;
        if (it < 53) {
            bLoad(it + 1, smemU + C1_SB0 + (uint32_t)nxt*C1_SB);
            if (tap == 8) {
                int nchunk = chunk + 1;
                haloLoad(nchunk, smemU + ((nchunk & 1) ? C1_HALO1 : C1_HALO0));
            }
            CP_COMMIT();
            CP_WAIT1();
        } else {
            CP_WAIT0();
        }
        __syncthreads();

        uint32_t hB = smemU + ((chunk & 1) ? C1_HALO1 : C1_HALO0);
        uint32_t bB = smemU + C1_SB0 + (uint32_t)cur*C1_SB + bOff;
        int dtap = (tap/3 - 1)*34 + (tap - (tap/3)*3 - 1);
        int hrow[4];
        #pragma unroll
        for (int mi = 0; mi < 4; mi++) hrow[mi] = hrow0[mi] + dtap;

        #pragma unroll
        for (int ks = 0; ks < 4; ks++) {
            uint32_t af[4][4], bf[4][2];
            #pragma unroll
            for (int mi = 0; mi < 4; mi++) {
                int seg = ks*2 + aseg;
                uint32_t addr = hB + (uint32_t)(hrow[mi]*128
                                 + ((seg ^ (hrow[mi] & 7))*16));
                ldm_x4(af[mi][0], af[mi][1], af[mi][2], af[mi][3], addr);
            }
            ldm_x4(bf[0][0], bf[0][1], bf[1][0], bf[1][1], bB + ks*32);
            ldm_x4(bf[2][0], bf[2][1], bf[3][0], bf[3][1],
                   bB + 16*ASTR*2 + ks*32);
            #pragma unroll
            for (int mi = 0; mi < 4; mi++)
                #pragma unroll
                for (int ni = 0; ni < 4; ni++)
                    mma16816(acc[mi][ni], af[mi], bf[ni]);
        }
        cur = nxt;
    }

    __syncthreads();
    if (tid < COUT) { sS[tid] = 0.f; sQ[tid] = 0.f; }
    __syncthreads();
    #pragma unroll
    for (int ni = 0; ni < 4; ni++) {
        int oc = nBase + ni*8 + tig*2;
        float s0=0.f,q0=0.f,s1=0.f,q1=0.f;
        #pragma unroll
        for (int mi = 0; mi < 4; mi++) {
            int px0 = mBase + mi*16 + grp;
            int px1 = px0 + 8;
            size_t gp0 = ((size_t)b*HW + (tileY + (px0>>5))*W + tileX + (px0&31))*NPAIR2;
            size_t gp1 = ((size_t)b*HW + (tileY + (px1>>5))*W + tileX + (px1&31))*NPAIR2;
            float a0 = acc[mi][ni][0], a1 = acc[mi][ni][1];
            float a2 = acc[mi][ni][2], a3 = acc[mi][ni][3];
            g_hraw[gp0 + (oc>>1)] = __floats2half2_rn(a0, a1);
            g_hraw[gp1 + (oc>>1)] = __floats2half2_rn(a2, a3);
            s0 += a0 + a2; q0 += a0*a0 + a2*a2;
            s1 += a1 + a3; q1 += a1*a1 + a3*a3;
        }
        atomicAdd(&sS[oc], s0);   atomicAdd(&sQ[oc], q0);
        atomicAdd(&sS[oc+1], s1); atomicAdd(&sQ[oc+1], q1);
    }
    __syncthreads();
    if (tid < COUT) {
        atomicAdd(&g_sum1[tid], sS[tid]);
        atomicAdd(&g_sq1[tid], sQ[tid]);
    }
}

// ---------------- kernel D: fused BN1-finalize + BN1+ReLU -------------------------
__global__ void k_bnrelu1(const float* __restrict__ g, const float* __restrict__ bb) {
    __shared__ float sc[COUT], sh[COUT];
    int tid = threadIdx.x;
    if (tid < COUT) {
        float s = g_sum1[tid], q = g_sq1[tid];
        float m = s / (float)NPIX;
        float v = q / (float)NPIX - m*m;
        float scv = g[tid] * rsqrtf(v + EPSV);
        sc[tid] = scv;
        sh[tid] = bb[tid] - m * scv;
    }
    __syncthreads();
    int idx = blockIdx.x * 256 + tid;
    if (idx >= BATCH*HW*16) return;
    uint4 q = ((const uint4*)g_hraw)[idx];
    int p0 = (idx & 15) * 4;
    uint32_t* e = (uint32_t*)&q;
    uint4 o;
    uint32_t* oe = (uint32_t*)&o;
    #pragma unroll
    for (int j = 0; j < 4; j++) {
        float2 f = __half22float2(*(__half2*)&e[j]);
        int c = 2*(p0 + j);
        float r0 = fmaxf(f.x * sc[c]   + sh[c],   0.f);
        float r1 = fmaxf(f.y * sc[c+1] + sh[c+1], 0.f);
        __half2 hv = __floats2half2_rn(r0, r1);
        oe[j] = *(uint32_t*)&hv;
    }
    ((uint4*)g_hh)[idx] = o;
}

// ---------------- kernel E: offset conv — per-chunk halo (unchanged) --------------
#define OC_SB (OPAD*ASTR*2)       // 4608
#define OC_HALO0 0
#define OC_HALO1 HB1
#define OC_SB0 (2*HB1)            // 52224
#define OFFC_SMEM (2*HB1 + 3*OC_SB)  // 66048
__global__ __launch_bounds__(256, 3) void k_offconv_mma(const float* __restrict__ bias) {
    extern __shared__ __align__(16) unsigned char dynsmem[];
    uint32_t smemU = (uint32_t)__cvta_generic_to_shared(dynsmem);

    int tid = threadIdx.x;
    int wid = tid >> 5, lane = tid & 31;
    int tileX = blockIdx.x * 32, tileY = blockIdx.y * 4;
    int b = blockIdx.z;
    int mBase = (wid & 3) * 32;
    int nBase = (wid >> 2) * 16;
    int grp = lane >> 2, tig = lane & 3;

    uint32_t bOff = (uint32_t)(((nBase + (lane & 7) + ((lane >> 4) & 1)*8)*ASTR
                                + ((lane >> 3) & 1)*8) * 2);
    int aseg = lane >> 4;
    int hrow0[2];
    #pragma unroll
    for (int mi = 0; mi < 2; mi++) {
        int px = mBase + mi*16 + (lane & 15);
        hrow0[mi] = ((px >> 5) + 1)*34 + (px & 31) + 1;
    }

    float acc[2][2][4];
    #pragma unroll
    for (int mi=0;mi<2;mi++)
        #pragma unroll
        for (int ni=0;ni<2;ni++)
            #pragma unroll
            for (int r=0;r<4;r++) acc[mi][ni][r]=0.f;

    int ocb = tid >> 3, segb = tid & 7;

    auto haloLoad = [&](int c, uint32_t hB) {
        #pragma unroll
        for (int k = 0; k < 7; k++) {
            int i = tid + k*256;
            if (i < HROWS1*8) {
                int ph = i >> 3, seg = i & 7;
                int hy = ph / 34, hx = ph - hy*34;
                int gy = tileY - 1 + hy, gx = tileX - 1 + hx;
                bool valid = (gy >= 0) && (gy < H) && (gx >= 0) && (gx < W);
                const __half2* src = g_hh
                    + ((size_t)(b*HW + (valid ? gy*W + gx : 0)))*NPAIR2 + c*32 + seg*4;
                cp_async16s(hB + (uint32_t)(ph*128 + ((seg ^ (ph & 7))*16)),
                            src, valid ? 16 : 0);
            }
        }
    };
    auto bLoad = [&](int it, uint32_t bB) {
        int chunk = it / 9, tap = it - chunk*9;
        const __half2* bsrc = g_wpoT + (size_t)tap*OPAD*NPAIR2 + chunk*32;
        cp_async16(bB + (uint32_t)((ocb*ASTR + segb*8) * 2),
                   bsrc + (size_t)ocb*NPAIR2 + segb*4);
    };

    haloLoad(0, smemU + OC_HALO0);
    bLoad(0, smemU + OC_SB0);
    CP_COMMIT();

    int cur = 0;
    for (int it = 0; it < 18; it++) {
        int chunk = it / 9, tap = it - chunk*9;
        int nxt = (cur == 2) ? 0 : cur + 1;
        if (it < 17) {
            bLoad(it + 1, smemU + OC_SB0 + (uint32_t)nxt*OC_SB);
            if (tap == 8) haloLoad(1, smemU + OC_HALO1);
            CP_COMMIT();
            CP_WAIT1();
        } else {
            CP_WAIT0();
        }
        __syncthreads();

        uint32_t hB = smemU + ((chunk & 1) ? OC_HALO1 : OC_HALO0);
        uint32_t bB = smemU + OC_SB0 + (uint32_t)cur*OC_SB + bOff;
        int dtap = (tap/3 - 1)*34 + (tap - (tap/3)*3 - 1);
        int hrow[2];
        #pragma unroll
        for (int mi = 0; mi < 2; mi++) hrow[mi] = hrow0[mi] + dtap;

        #pragma unroll
        for (int ks = 0; ks < 4; ks++) {
            uint32_t af[2][4], bf[2][2];
            #pragma unroll
            for (int mi = 0; mi < 2; mi++) {
                int seg = ks*2 + aseg;
                uint32_t addr = hB + (uint32_t)(hrow[mi]*128
                                 + ((seg ^ (hrow[mi] & 7))*16));
                ldm_x4(af[mi][0], af[mi][1], af[mi][2], af[mi][3], addr);
            }
            ldm_x4(bf[0][0], bf[0][1], bf[1][0], bf[1][1], bB + ks*32);
            #pragma unroll
            for (int mi = 0; mi < 2; mi++)
                #pragma unroll
                for (int ni = 0; ni < 2; ni++)
                    mma16816(acc[mi][ni], af[mi], bf[ni]);
        }
        cur = nxt;
    }

    #pragma unroll
    for (int ni = 0; ni < 2; ni++) {
        int oc = nBase + ni*8 + tig*2;
        if (oc >= 18) continue;
        float b0 = bias[oc];
        float b1 = (oc + 1 < 18) ? bias[oc+1] : 0.f;
        #pragma unroll
        for (int mi = 0; mi < 2; mi++) {
            int px0 = mBase + mi*16 + grp;
            int px1 = px0 + 8;
            int y0 = tileY + (px0>>5), x0 = tileX + (px0&31);
            int y1 = tileY + (px1>>5), x1 = tileX + (px1&31);
            g_off[((size_t)(b*18 + oc)*HW) + y0*W + x0] = acc[mi][ni][0] + b0;
            g_off[((size_t)(b*18 + oc)*HW) + y1*W + x1] = acc[mi][ni][2] + b0;
            if (oc + 1 < 18) {
                g_off[((size_t)(b*18 + oc + 1)*HW) + y0*W + x0] = acc[mi][ni][1] + b1;
                g_off[((size_t)(b*18 + oc + 1)*HW) + y1*W + x1] = acc[mi][ni][3] + b1;
            }
        }
    }
}

// ---------------- kernel F: deform conv — HFMA2 blend gather ----------------------
#define D_HALO   0
#define D_SA     36864
#define D_SB     73728
#define D_SS     110592
#define D_SQ     111104
#define DEF_SMEM 111616
__global__ __launch_bounds__(256, 2) void k_deform_mma(const float* __restrict__ db) {
    extern __shared__ __align__(16) unsigned char dyn[];
    const char* halo = (const char*)(dyn + D_HALO);
    float* sS = (float*)(dyn + D_SS);
    float* sQ = (float*)(dyn + D_SQ);
    uint32_t smemU = (uint32_t)__cvta_generic_to_shared(dyn);
    uint32_t haloU = smemU + D_HALO;
    uint32_t sA_u  = smemU + D_SA;
    uint32_t sB_u  = smemU + D_SB;
    __half* sA = (__half*)(dyn + D_SA);

    int tid = threadIdx.x;
    int wid = tid >> 5, lane = tid & 31;
    int tileX = blockIdx.x * 32, tileY = blockIdx.y * 4;
    int b = blockIdx.z;
    int mBase = (wid & 1) * 64;
    int nBase = (wid >> 1) * 32;
    int grp = lane >> 2, tig = lane & 3;
    int hY0 = tileY - 2, hX0 = tileX - 2;

    uint32_t aOff = (uint32_t)(((mBase + (lane & 15))*ASTR + (lane >> 4)*8) * 2);
    uint32_t bOff = (uint32_t)(((nBase + (lane & 7) + ((lane >> 4) & 1)*8)*ASTR
                                + ((lane >> 3) & 1)*8) * 2);

    float acc[4][4][4];
    #pragma unroll
    for (int mi=0;mi<4;mi++)
        #pragma unroll
        for (int ni=0;ni<4;ni++)
            #pragma unroll
            for (int r=0;r<4;r++) acc[mi][ni][r]=0.f;

    int px_s = tid & 127;
    int half_s = tid >> 7;
    int ocb = tid >> 3, segb = tid & 7;
    int py_s = tileY + (px_s >> 5), pxg_s = tileX + (px_s & 31);

    auto haloLoad = [&](int chunk) {
        #pragma unroll
        for (int k = 0; k < 9; k++) {
            int i = tid + k*256;
            int ph = i >> 3, seg = i & 7;
            int yr = min(max(hY0 + ph/36, 0), H-1);
            int xr = min(max(hX0 + ph%36, 0), W-1);
            const __half2* src = g_hh + ((size_t)(b*HW + yr*W + xr))*NPAIR2
                                 + chunk*32 + seg*4;
            cp_async16(haloU + (uint32_t)(ph*128 + ((seg ^ (ph & 7))*16)), src);
        }
    };
    auto bLoad = [&](int it) {
        int chunk = it / 9, tap = it - chunk*9;
        const __half2* bsrc = g_wp2T + (size_t)tap*COUT*NPAIR2 + chunk*32;
        uint32_t bB = sB_u + (uint32_t)(it & 1)*18432;
        #pragma unroll
        for (int j = 0; j < 4; j++) {
            int oc = ocb + j*32;
            cp_async16(bB + (uint32_t)((oc*ASTR + segb*8) * 2),
                       bsrc + (size_t)oc*NPAIR2 + segb*4);
        }
    };

    auto gather = [&](int it, int buf) {
        int chunk = it / 9, tap = it - chunk*9;
        float dy = g_off[((size_t)(b*18 + 2*tap    )*HW) + py_s*W + pxg_s];
        float dx = g_off[((size_t)(b*18 + 2*tap + 1)*HW) + py_s*W + pxg_s];
        float py  = (float)py_s + (float)(tap/3 - 1) + dy;
        float pxx = (float)pxg_s + (float)(tap - (tap/3)*3 - 1) + dx;
        float y0f = floorf(py), x0f = floorf(pxx);
        float wy = py - y0f, wx = pxx - x0f;
        int yi = (int)y0f, xi = (int)x0f;
        bool yv0 = (yi >= 0) && (yi < H);
        bool yv1 = (yi+1 >= 0) && (yi+1 < H);
        bool xv0 = (xi >= 0) && (xi < W);
        bool xv1 = (xi+1 >= 0) && (xi+1 < W);
        float w00 = (yv0 && xv0) ? (1.f-wy)*(1.f-wx) : 0.f;
        float w01 = (yv0 && xv1) ? (1.f-wy)*wx       : 0.f;
        float w10 = (yv1 && xv0) ? wy*(1.f-wx)       : 0.f;
        float w11 = (yv1 && xv1) ? wy*wx             : 0.f;
        __half2 w00h = __float2half2_rn(w00);
        __half2 w01h = __float2half2_rn(w01);
        __half2 w10h = __float2half2_rn(w10);
        __half2 w11h = __float2half2_rn(w11);
        int ry0 = min(max(yi,   0), H-1) - hY0;
        int ry1 = min(max(yi+1, 0), H-1) - hY0;
        int rx0 = min(max(xi,   0), W-1) - hX0;
        int rx1 = min(max(xi+1, 0), W-1) - hX0;
        bool inHalo = (ry0 >= 0) && (ry1 < 8) && (rx0 >= 0) && (rx1 < 36);
        int segBase = half_s*4;
        uint32_t res[4][4];
        if (inHalo) {
            int h00 = ry0*36 + rx0, h01 = ry0*36 + rx1;
            int h10 = ry1*36 + rx0, h11 = ry1*36 + rx1;
            #pragma unroll
            for (int j = 0; j < 4; j++) {
                int seg = segBase + j;
                uint4 q0 = *(const uint4*)(halo + h00*128 + ((seg ^ (h00 & 7))*16));
                uint4 q1 = *(const uint4*)(halo + h01*128 + ((seg ^ (h01 & 7))*16));
                uint4 q2 = *(const uint4*)(halo + h10*128 + ((seg ^ (h10 & 7))*16));
                uint4 q3 = *(const uint4*)(halo + h11*128 + ((seg ^ (h11 & 7))*16));
                const uint32_t* a0 = (const uint32_t*)&q0;
                const uint32_t* a1 = (const uint32_t*)&q1;
                const uint32_t* a2 = (const uint32_t*)&q2;
                const uint32_t* a3 = (const uint32_t*)&q3;
                #pragma unroll
                for (int e = 0; e < 4; e++) {
                    __half2 v = __hmul2(*(__half2*)&a0[e], w00h);
                    v = __hfma2(*(__half2*)&a1[e], w01h, v);
                    v = __hfma2(*(__half2*)&a2[e], w10h, v);
                    v = __hfma2(*(__half2*)&a3[e], w11h, v);
                    res[j][e] = *(uint32_t*)&v;
                }
            }
        } else {
            int pb = chunk*32 + half_s*16;
            const uint4* p0 = (const uint4*)(g_hh + ((size_t)b*HW + (hY0+ry0)*W + hX0+rx0)*NPAIR2 + pb);
            const uint4* p1 = (const uint4*)(g_hh + ((size_t)b*HW + (hY0+ry0)*W + hX0+rx1)*NPAIR2 + pb);
            const uint4* p2 = (const uint4*)(g_hh + ((size_t)b*HW + (hY0+ry1)*W + hX0+rx0)*NPAIR2 + pb);
            const uint4* p3 = (const uint4*)(g_hh + ((size_t)b*HW + (hY0+ry1)*W + hX0+rx1)*NPAIR2 + pb);
            #pragma unroll
            for (int j = 0; j < 4; j++) {
                uint4 q0 = p0[j], q1 = p1[j], q2 = p2[j], q3 = p3[j];
                const uint32_t* a0 = (const uint32_t*)&q0;
                const uint32_t* a1 = (const uint32_t*)&q1;
                const uint32_t* a2 = (const uint32_t*)&q2;
                const uint32_t* a3 = (const uint32_t*)&q3;
                #pragma unroll
                for (int e = 0; e < 4; e++) {
                    __half2 v = __hmul2(*(__half2*)&a0[e], w00h);
                    v = __hfma2(*(__half2*)&a1[e], w01h, v);
                    v = __hfma2(*(__half2*)&a2[e], w10h, v);
                    v = __hfma2(*(__half2*)&a3[e], w11h, v);
                    res[j][e] = *(uint32_t*)&v;
                }
            }
        }
        __half* dst = sA + (size_t)buf*(128*ASTR) + px_s*ASTR + half_s*32;
        #pragma unroll
        for (int j = 0; j < 4; j++)
            *(uint4*)(dst + j*8) = *(uint4*)res[j];
    };

    auto mmaStep = [&](int it) {
        uint32_t aB = sA_u + (uint32_t)(it & 1)*18432 + aOff;
        uint32_t bB = sB_u + (uint32_t)(it & 1)*18432 + bOff;
        #pragma unroll
        for (int ks = 0; ks < 4; ks++) {
            uint32_t af[4][4], bf[4][2];
            #pragma unroll
            for (int mi = 0; mi < 4; mi++)
                ldm_x4(af[mi][0], af[mi][1], af[mi][2], af[mi][3],
                       aB + mi*(16*ASTR*2) + ks*32);
            ldm_x4(bf[0][0], bf[0][1], bf[1][0], bf[1][1], bB + ks*32);
            ldm_x4(bf[2][0], bf[2][1], bf[3][0], bf[3][1],
                   bB + 16*ASTR*2 + ks*32);
            #pragma unroll
            for (int mi = 0; mi < 4; mi++)
                #pragma unroll
                for (int ni = 0; ni < 4; ni++)
                    mma16816(acc[mi][ni], af[mi], bf[ni]);
        }
    };

    haloLoad(0);
    bLoad(0);
    CP_COMMIT();
    CP_WAIT0();
    __syncthreads();
    gather(0, 0);

    for (int it = 0; it < 18; it++) {
        __syncthreads();
        if (it == 8) {
            haloLoad(1);
            bLoad(9);
            CP_COMMIT();
            mmaStep(8);
            CP_WAIT0();
            continue;
        }
        if (it == 9) {
            gather(9, 1);
            bLoad(10);
            CP_COMMIT();
            gather(10, 0);
            CP_WAIT1();
            __syncthreads();
            mmaStep(9);
            continue;
        }
        if (it < 17) {
            bLoad(it+1);
            CP_COMMIT();
            if (it+1 != 9 && it+1 != 10) gather(it+1, (it+1) & 1);
            CP_WAIT1();
        } else {
            CP_WAIT0();
        }
        __syncthreads();
        mmaStep(it);
    }

    __syncthreads();
    if (tid < COUT) { sS[tid] = 0.f; sQ[tid] = 0.f; }
    __syncthreads();
    #pragma unroll
    for (int ni = 0; ni < 4; ni++) {
        int oc = nBase + ni*8 + tig*2;
        float b0 = db[oc], b1 = db[oc+1];
        float s0=0.f,q0=0.f,s1=0.f,q1=0.f;
        #pragma unroll
        for (int mi = 0; mi < 4; mi++) {
            int px0 = mBase + mi*16 + grp;
            int px1 = px0 + 8;
            size_t gp0 = ((size_t)b*HW + (tileY + (px0>>5))*W + tileX + (px0&31))*COUT;
            size_t gp1 = ((size_t)b*HW + (tileY + (px1>>5))*W + tileX + (px1&31))*COUT;
            float a0 = acc[mi][ni][0] + b0, a1 = acc[mi][ni][1] + b1;
            float a2 = acc[mi][ni][2] + b0, a3 = acc[mi][ni][3] + b1;
            *(float2*)&g_y[gp0 + oc] = make_float2(a0, a1);
            *(float2*)&g_y[gp1 + oc] = make_float2(a2, a3);
            s0 += a0 + a2; q0 += a0*a0 + a2*a2;
            s1 += a1 + a3; q1 += a1*a1 + a3*a3;
        }
        atomicAdd(&sS[oc], s0);   atomicAdd(&sQ[oc], q0);
        atomicAdd(&sS[oc+1], s1); atomicAdd(&sQ[oc+1], q1);
    }
    __syncthreads();
    if (tid < COUT) {
        atomicAdd(&g_sum2[tid], sS[tid]);
        atomicAdd(&g_sq2[tid], sQ[tid]);
    }
}

// ---------------- kernel H: fused BN2-finalize + BN2+ReLU -> planar out -----------
__global__ __launch_bounds__(256) void k_bnrelu2(const float* __restrict__ g,
                                                 const float* __restrict__ bb,
                                                 float* __restrict__ out) {
    __shared__ float s[32][129];
    __shared__ float sc[COUT], sh[COUT];
    int tid = threadIdx.x;
    if (tid < COUT) {
        float su = g_sum2[tid], q = g_sq2[tid];
        float m = su / (float)NPIX;
        float v = q / (float)NPIX - m*m;
        float scv = g[tid] * rsqrtf(v + EPSV);
        sc[tid] = scv;
        sh[tid] = bb[tid] - m * scv;
    }
    int px0 = blockIdx.x * 32;
    int b = blockIdx.y;
    #pragma unroll
    for (int j = 0; j < 16; j++) {
        int idx = tid + j*256;
        int pxl = idx >> 7, c = idx & 127;
        s[pxl][c] = g_y[((size_t)b*HW + px0 + pxl)*COUT + c];
    }
    __syncthreads();
    #pragma unroll
    for (int j = 0; j < 16; j++) {
        int idx = tid + j*256;
        int c = idx >> 5, pxl = idx & 31;
        float v = s[pxl][c] * sc[c] + sh[c];
        out[((size_t)(b*COUT + c)*HW) + px0 + pxl] = fmaxf(v, 0.f);
    }
}

// ---------------- launch -----------------------------------------------------------
extern "C" void kernel_launch(void* const* d_in, const int* in_sizes, int n_in,
                              void* d_out, int out_size) {
    const float* x       = (const float*)d_in[0];
    const float* skip    = (const float*)d_in[1];
    const float* conv1_w = (const float*)d_in[2];
    const float* bn1_g   = (const float*)d_in[3];
    const float* bn1_b   = (const float*)d_in[4];
    const float* off_w   = (const float*)d_in[5];
    const float* off_b   = (const float*)d_in[6];
    const float* def_w   = (const float*)d_in[7];
    const float* def_b   = (const float*)d_in[8];
    const float* bn2_g   = (const float*)d_in[9];
    const float* bn2_b   = (const float*)d_in[10];
    float* out = (float*)d_out;

    static bool attrDone = false;
    if (!attrDone) {
        cudaFuncSetAttribute(k_conv1_mma,
                             cudaFuncAttributeMaxDynamicSharedMemorySize, CONV1_SMEM);
        cudaFuncSetAttribute(k_offconv_mma,
                             cudaFuncAttributeMaxDynamicSharedMemorySize, OFFC_SMEM);
        cudaFuncSetAttribute(k_deform_mma,
                             cudaFuncAttributeMaxDynamicSharedMemorySize, DEF_SMEM);
        attrDone = true;
    }

    k_prep_upcat<<<NPREP_BLK + NUP_BLK, 256>>>(conv1_w, def_w, off_w, x, skip);

    k_conv1_mma<<<dim3(W/32, H/4, BATCH), 256, CONV1_SMEM>>>();

    int nhp = BATCH*HW*16;
    k_bnrelu1<<<(nhp + 255)/256, 256>>>(bn1_g, bn1_b);

    k_offconv_mma<<<dim3(W/32, H/4, BATCH), 256, OFFC_SMEM>>>(off_b);

    k_deform_mma<<<dim3(W/32, H/4, BATCH), 256, DEF_SMEM>>>(def_b);

    k_bnrelu2<<<dim3(HW/32, BATCH), 256>>>(bn2_g, bn2_b, out);
}

// round 17
// speedup vs baseline: 1.0177x; 1.0029x over previous
#include <cuda_runtime.h>
#include <cuda_fp16.h>
#include <cstdint>

#define BATCH 4
#define H 128
#define W 128
#define HW (H*W)
#define CIN_X 256
#define CSKIP 128
#define CCAT 384
#define NPAIR (CCAT/2)   // 192
#define COUT 128
#define NPAIR2 (COUT/2)  // 64
#define OPAD 32
#define NPIX (BATCH*HW)
#define EPSV 1e-5f
#define ASTR 72          // halves per smem row (144B)

#define NW1 (9*COUT*NPAIR)    // 221184
#define NW2 (9*COUT*NPAIR2)   // 73728
#define NW3 (9*OPAD*NPAIR2)   // 18432
#define NPREP_BLK ((NW1 + NW2 + NW3 + 255)/256)
#define NUP_BLK   ((BATCH*HW*(NPAIR/8) + 255)/256)

// ---------------- scratch ------------------------------------------------------
__device__ __align__(16) __half   g_cat[(size_t)BATCH*HW*CCAT];     // CH-LAST fp16
__device__ __align__(16) __half2  g_wpT[NW1];                       // conv1 w [tap][oc][pair]
__device__ __align__(16) __half2  g_wp2T[NW2];                      // def w
__device__ __align__(16) __half2  g_wpoT[NW3];                      // off w (padded)
__device__ __align__(16) __half2  g_hraw[(size_t)BATCH*HW*NPAIR2];  // conv1 out, ch-last fp16
__device__ __align__(16) __half2  g_hh[(size_t)BATCH*HW*NPAIR2];    // BN1+ReLU h, ch-last
__device__ float   g_off[BATCH*18*HW];
__device__ float   g_y[(size_t)BATCH*HW*COUT];
__device__ float g_sum1[COUT], g_sq1[COUT], g_sum2[COUT], g_sq2[COUT];

// ---------------- helpers ------------------------------------------------------
__device__ __forceinline__ void ldm_x4(uint32_t& r0, uint32_t& r1, uint32_t& r2,
                                       uint32_t& r3, uint32_t addr) {
    asm volatile("ldmatrix.sync.aligned.m8n8.x4.shared.b16 {%0,%1,%2,%3}, [%4];"
                 : "=r"(r0), "=r"(r1), "=r"(r2), "=r"(r3) : "r"(addr));
}
__device__ __forceinline__ void mma16816(float* c, const uint32_t* a, const uint32_t* b) {
    asm volatile(
        "mma.sync.aligned.m16n8k16.row.col.f32.f16.f16.f32 "
        "{%0,%1,%2,%3}, {%4,%5,%6,%7}, {%8,%9}, {%0,%1,%2,%3};"
        : "+f"(c[0]), "+f"(c[1]), "+f"(c[2]), "+f"(c[3])
        : "r"(a[0]), "r"(a[1]), "r"(a[2]), "r"(a[3]), "r"(b[0]), "r"(b[1]));
}
__device__ __forceinline__ void cp_async16(uint32_t dst, const void* src) {
    asm volatile("cp.async.cg.shared.global [%0], [%1], 16;"
                 :: "r"(dst), "l"(src) : "memory");
}
__device__ __forceinline__ void cp_async16s(uint32_t dst, const void* src, int ssize) {
    asm volatile("cp.async.cg.shared.global [%0], [%1], 16, %2;"
                 :: "r"(dst), "l"(src), "r"(ssize) : "memory");
}
#define CP_COMMIT() asm volatile("cp.async.commit_group;" ::: "memory")
#define CP_WAIT1()  asm volatile("cp.async.wait_group 1;" ::: "memory")
#define CP_WAIT0()  asm volatile("cp.async.wait_group 0;" ::: "memory")

// ---------------- kernel P: fused zero + weight packs + upcat (8 pairs/thread) --
__global__ void k_prep_upcat(const float* __restrict__ cw, const float* __restrict__ dw,
                             const float* __restrict__ ow, const float* __restrict__ x,
                             const float* __restrict__ skip) {
    if (blockIdx.x < NPREP_BLK) {
        int idx = blockIdx.x * 256 + threadIdx.x;
        if (idx < COUT) { g_sum1[idx]=0.f; g_sq1[idx]=0.f; g_sum2[idx]=0.f; g_sq2[idx]=0.f; }
        if (idx < NW1) {
            int p   = idx % NPAIR;
            int oc  = (idx / NPAIR) % COUT;
            int tap = idx / (NPAIR*COUT);
            float w0 = cw[((size_t)oc*CCAT + 2*p    )*9 + tap];
            float w1 = cw[((size_t)oc*CCAT + 2*p + 1)*9 + tap];
            g_wpT[idx] = __floats2half2_rn(w0, w1);
        } else if (idx < NW1 + NW2) {
            int j = idx - NW1;
            int p   = j % NPAIR2;
            int oc  = (j / NPAIR2) % COUT;
            int tap = j / (NPAIR2*COUT);
            float w0 = dw[((size_t)oc*COUT + 2*p    )*9 + tap];
            float w1 = dw[((size_t)oc*COUT + 2*p + 1)*9 + tap];
            g_wp2T[j] = __floats2half2_rn(w0, w1);
        } else if (idx < NW1 + NW2 + NW3) {
            int j = idx - NW1 - NW2;
            int p   = j % NPAIR2;
            int oc  = (j / NPAIR2) % OPAD;
            int tap = j / (NPAIR2*OPAD);
            float w0 = 0.f, w1 = 0.f;
            if (oc < 18) {
                w0 = ow[((size_t)oc*COUT + 2*p    )*9 + tap];
                w1 = ow[((size_t)oc*COUT + 2*p + 1)*9 + tap];
            }
            g_wpoT[j] = __floats2half2_rn(w0, w1);
        }
        return;
    }
    int idx = (blockIdx.x - NPREP_BLK) * 256 + threadIdx.x;
    if (idx >= BATCH*HW*(NPAIR/8)) return;
    int xc = idx % W;
    int y  = (idx / W) % H;
    int g8 = (idx / HW) % (NPAIR/8);
    int b  = idx / (HW*(NPAIR/8));
    int p0 = g8 * 8;
    __half2 res[8];
    if (p0 < CSKIP/2) {
        const float* sp = skip + ((size_t)(b*CSKIP + 2*p0)*HW) + y*W + xc;
        #pragma unroll
        for (int j = 0; j < 8; j++) {
            float v0 = sp[(size_t)(2*j  )*HW];
            float v1 = sp[(size_t)(2*j+1)*HW];
            res[j] = __floats2half2_rn(v0, v1);
        }
    } else {
        int ci0 = 2*p0 - CSKIP;
        float fy = (float)y  * (63.0f / 127.0f);
        float fx = (float)xc * (63.0f / 127.0f);
        int y0 = (int)fy, x0 = (int)fx;
        float wy = fy - (float)y0, wx = fx - (float)x0;
        int y1 = min(y0+1, 63), x1 = min(x0+1, 63);
        int i00 = y0*64+x0, i01 = y0*64+x1, i10 = y1*64+x0, i11 = y1*64+x1;
        float w00 = (1.f-wy)*(1.f-wx), w01 = (1.f-wy)*wx;
        float w10 = wy*(1.f-wx), w11 = wy*wx;
        const float* xp = x + (size_t)(b*CIN_X + ci0)*4096;
        #pragma unroll
        for (int j = 0; j < 8; j++) {
            const float* c0p = xp + (size_t)(2*j)*4096;
            const float* c1p = c0p + 4096;
            float v0 = c0p[i00]*w00 + c0p[i01]*w01 + c0p[i10]*w10 + c0p[i11]*w11;
            float v1 = c1p[i00]*w00 + c1p[i01]*w01 + c1p[i10]*w10 + c1p[i11]*w11;
            res[j] = __floats2half2_rn(v0, v1);
        }
    }
    __half* outp = &g_cat[((size_t)(b*HW + y*W + xc))*CCAT + p0*2];
    *(uint4*)outp       = *(uint4*)&res[0];
    *(uint4*)(outp + 8) = *(uint4*)&res[4];
}

// ---------------- kernel B: conv1 — depth-3 B ring (unchanged) ------------------
#define HROWS1 204
#define HB1 (HROWS1*128)          // 26112
#define C1_SB 18432
#define C1_HALO0 0
#define C1_HALO1 HB1
#define C1_SB0 (2*HB1)            // 52224
#define C1_SS  (2*HB1 + 3*C1_SB)  // 107520
#define CONV1_SMEM (C1_SS + 1024)
__global__ __launch_bounds__(256, 2) void k_conv1_mma() {
    extern __shared__ __align__(16) unsigned char dynsmem[];
    uint32_t smemU = (uint32_t)__cvta_generic_to_shared(dynsmem);
    float* sS = (float*)(dynsmem + C1_SS);
    float* sQ = sS + COUT;

    int tid = threadIdx.x;
    int wid = tid >> 5, lane = tid & 31;
    int tileX = blockIdx.x * 32, tileY = blockIdx.y * 4;
    int b = blockIdx.z;
    int mBase = (wid & 1) * 64;
    int nBase = (wid >> 1) * 32;
    int grp = lane >> 2, tig = lane & 3;

    uint32_t bOff = (uint32_t)(((nBase + (lane & 7) + ((lane >> 4) & 1)*8)*ASTR
                                + ((lane >> 3) & 1)*8) * 2);
    int aseg = lane >> 4;
    int hrow0[4];
    #pragma unroll
    for (int mi = 0; mi < 4; mi++) {
        int px = mBase + mi*16 + (lane & 15);
        hrow0[mi] = ((px >> 5) + 1)*34 + (px & 31) + 1;
    }

    float acc[4][4][4];
    #pragma unroll
    for (int mi=0;mi<4;mi++)
        #pragma unroll
        for (int ni=0;ni<4;ni++)
            #pragma unroll
            for (int r=0;r<4;r++) acc[mi][ni][r]=0.f;

    int ocb = tid >> 3, segb = tid & 7;

    auto haloLoad = [&](int c, uint32_t hB) {
        #pragma unroll
        for (int k = 0; k < 7; k++) {
            int i = tid + k*256;
            if (i < HROWS1*8) {
                int ph = i >> 3, seg = i & 7;
                int hy = ph / 34, hx = ph - hy*34;
                int gy = tileY - 1 + hy, gx = tileX - 1 + hx;
                bool valid = (gy >= 0) && (gy < H) && (gx >= 0) && (gx < W);
                const __half* src = g_cat
                    + ((size_t)(b*HW + (valid ? gy*W + gx : 0)))*CCAT + c*64 + seg*8;
                cp_async16s(hB + (uint32_t)(ph*128 + ((seg ^ (ph & 7))*16)),
                            src, valid ? 16 : 0);
            }
        }
    };
    auto bLoad = [&](int it, uint32_t bB) {
        int chunk = it / 9, tap = it - chunk*9;
        const __half2* bsrc = g_wpT + (size_t)tap*COUT*NPAIR + chunk*32;
        #pragma unroll
        for (int j = 0; j < 4; j++) {
            int oc = ocb + j*32;
            cp_async16(bB + (uint32_t)((oc*ASTR + segb*8) * 2),
                       bsrc + (size_t)oc*NPAIR + segb*4);
        }
    };

    haloLoad(0, smemU + C1_HALO0);
    bLoad(0, smemU + C1_SB0);
    CP_COMMIT();

    int cur = 0;
    for (int it = 0; it < 54; it++) {
        int chunk = it / 9, tap = it - chunk*9;
        int nxt = (cur == 2) ? 0 : cur + 1;
        if (it < 53) {
            bLoad(it + 1, smemU + C1_SB0 + (uint32_t)nxt*C1_SB);
            if (tap == 8) {
                int nchunk = chunk + 1;
                haloLoad(nchunk, smemU + ((nchunk & 1) ? C1_HALO1 : C1_HALO0));
            }
            CP_COMMIT();
            CP_WAIT1();
        } else {
            CP_WAIT0();
        }
        __syncthreads();

        uint32_t hB = smemU + ((chunk & 1) ? C1_HALO1 : C1_HALO0);
        uint32_t bB = smemU + C1_SB0 + (uint32_t)cur*C1_SB + bOff;
        int dtap = (tap/3 - 1)*34 + (tap - (tap/3)*3 - 1);
        int hrow[4];
        #pragma unroll
        for (int mi = 0; mi < 4; mi++) hrow[mi] = hrow0[mi] + dtap;

        #pragma unroll
        for (int ks = 0; ks < 4; ks++) {
            uint32_t af[4][4], bf[4][2];
            #pragma unroll
            for (int mi = 0; mi < 4; mi++) {
                int seg = ks*2 + aseg;
                uint32_t addr = hB + (uint32_t)(hrow[mi]*128
                                 + ((seg ^ (hrow[mi] & 7))*16));
                ldm_x4(af[mi][0], af[mi][1], af[mi][2], af[mi][3], addr);
            }
            ldm_x4(bf[0][0], bf[0][1], bf[1][0], bf[1][1], bB + ks*32);
            ldm_x4(bf[2][0], bf[2][1], bf[3][0], bf[3][1],
                   bB + 16*ASTR*2 + ks*32);
            #pragma unroll
            for (int mi = 0; mi < 4; mi++)
                #pragma unroll
                for (int ni = 0; ni < 4; ni++)
                    mma16816(acc[mi][ni], af[mi], bf[ni]);
        }
        cur = nxt;
    }

    __syncthreads();
    if (tid < COUT) { sS[tid] = 0.f; sQ[tid] = 0.f; }
    __syncthreads();
    #pragma unroll
    for (int ni = 0; ni < 4; ni++) {
        int oc = nBase + ni*8 + tig*2;
        float s0=0.f,q0=0.f,s1=0.f,q1=0.f;
        #pragma unroll
        for (int mi = 0; mi < 4; mi++) {
            int px0 = mBase + mi*16 + grp;
            int px1 = px0 + 8;
            size_t gp0 = ((size_t)b*HW + (tileY + (px0>>5))*W + tileX + (px0&31))*NPAIR2;
            size_t gp1 = ((size_t)b*HW + (tileY + (px1>>5))*W + tileX + (px1&31))*NPAIR2;
            float a0 = acc[mi][ni][0], a1 = acc[mi][ni][1];
            float a2 = acc[mi][ni][2], a3 = acc[mi][ni][3];
            g_hraw[gp0 + (oc>>1)] = __floats2half2_rn(a0, a1);
            g_hraw[gp1 + (oc>>1)] = __floats2half2_rn(a2, a3);
            s0 += a0 + a2; q0 += a0*a0 + a2*a2;
            s1 += a1 + a3; q1 += a1*a1 + a3*a3;
        }
        atomicAdd(&sS[oc], s0);   atomicAdd(&sQ[oc], q0);
        atomicAdd(&sS[oc+1], s1); atomicAdd(&sQ[oc+1], q1);
    }
    __syncthreads();
    if (tid < COUT) {
        atomicAdd(&g_sum1[tid], sS[tid]);
        atomicAdd(&g_sq1[tid], sQ[tid]);
    }
}

// ---------------- kernel D: fused BN1-finalize + BN1+ReLU -------------------------
__global__ void k_bnrelu1(const float* __restrict__ g, const float* __restrict__ bb) {
    __shared__ float sc[COUT], sh[COUT];
    int tid = threadIdx.x;
    if (tid < COUT) {
        float s = g_sum1[tid], q = g_sq1[tid];
        float m = s / (float)NPIX;
        float v = q / (float)NPIX - m*m;
        float scv = g[tid] * rsqrtf(v + EPSV);
        sc[tid] = scv;
        sh[tid] = bb[tid] - m * scv;
    }
    __syncthreads();
    int idx = blockIdx.x * 256 + tid;
    if (idx >= BATCH*HW*16) return;
    uint4 q = ((const uint4*)g_hraw)[idx];
    int p0 = (idx & 15) * 4;
    uint32_t* e = (uint32_t*)&q;
    uint4 o;
    uint32_t* oe = (uint32_t*)&o;
    #pragma unroll
    for (int j = 0; j < 4; j++) {
        float2 f = __half22float2(*(__half2*)&e[j]);
        int c = 2*(p0 + j);
        float r0 = fmaxf(f.x * sc[c]   + sh[c],   0.f);
        float r1 = fmaxf(f.y * sc[c+1] + sh[c+1], 0.f);
        __half2 hv = __floats2half2_rn(r0, r1);
        oe[j] = *(uint32_t*)&hv;
    }
    ((uint4*)g_hh)[idx] = o;
}

// ---------------- kernel E: offset conv — per-chunk halo (unchanged) --------------
#define OC_SB (OPAD*ASTR*2)       // 4608
#define OC_HALO0 0
#define OC_HALO1 HB1
#define OC_SB0 (2*HB1)            // 52224
#define OFFC_SMEM (2*HB1 + 3*OC_SB)  // 66048
__global__ __launch_bounds__(256, 3) void k_offconv_mma(const float* __restrict__ bias) {
    extern __shared__ __align__(16) unsigned char dynsmem[];
    uint32_t smemU = (uint32_t)__cvta_generic_to_shared(dynsmem);

    int tid = threadIdx.x;
    int wid = tid >> 5, lane = tid & 31;
    int tileX = blockIdx.x * 32, tileY = blockIdx.y * 4;
    int b = blockIdx.z;
    int mBase = (wid & 3) * 32;
    int nBase = (wid >> 2) * 16;
    int grp = lane >> 2, tig = lane & 3;

    uint32_t bOff = (uint32_t)(((nBase + (lane & 7) + ((lane >> 4) & 1)*8)*ASTR
                                + ((lane >> 3) & 1)*8) * 2);
    int aseg = lane >> 4;
    int hrow0[2];
    #pragma unroll
    for (int mi = 0; mi < 2; mi++) {
        int px = mBase + mi*16 + (lane & 15);
        hrow0[mi] = ((px >> 5) + 1)*34 + (px & 31) + 1;
    }

    float acc[2][2][4];
    #pragma unroll
    for (int mi=0;mi<2;mi++)
        #pragma unroll
        for (int ni=0;ni<2;ni++)
            #pragma unroll
            for (int r=0;r<4;r++) acc[mi][ni][r]=0.f;

    int ocb = tid >> 3, segb = tid & 7;

    auto haloLoad = [&](int c, uint32_t hB) {
        #pragma unroll
        for (int k = 0; k < 7; k++) {
            int i = tid + k*256;
            if (i < HROWS1*8) {
                int ph = i >> 3, seg = i & 7;
                int hy = ph / 34, hx = ph - hy*34;
                int gy = tileY - 1 + hy, gx = tileX - 1 + hx;
                bool valid = (gy >= 0) && (gy < H) && (gx >= 0) && (gx < W);
                const __half2* src = g_hh
                    + ((size_t)(b*HW + (valid ? gy*W + gx : 0)))*NPAIR2 + c*32 + seg*4;
                cp_async16s(hB + (uint32_t)(ph*128 + ((seg ^ (ph & 7))*16)),
                            src, valid ? 16 : 0);
            }
        }
    };
    auto bLoad = [&](int it, uint32_t bB) {
        int chunk = it / 9, tap = it - chunk*9;
        const __half2* bsrc = g_wpoT + (size_t)tap*OPAD*NPAIR2 + chunk*32;
        cp_async16(bB + (uint32_t)((ocb*ASTR + segb*8) * 2),
                   bsrc + (size_t)ocb*NPAIR2 + segb*4);
    };

    haloLoad(0, smemU + OC_HALO0);
    bLoad(0, smemU + OC_SB0);
    CP_COMMIT();

    int cur = 0;
    for (int it = 0; it < 18; it++) {
        int chunk = it / 9, tap = it - chunk*9;
        int nxt = (cur == 2) ? 0 : cur + 1;
        if (it < 17) {
            bLoad(it + 1, smemU + OC_SB0 + (uint32_t)nxt*OC_SB);
            if (tap == 8) haloLoad(1, smemU + OC_HALO1);
            CP_COMMIT();
            CP_WAIT1();
        } else {
            CP_WAIT0();
        }
        __syncthreads();

        uint32_t hB = smemU + ((chunk & 1) ? OC_HALO1 : OC_HALO0);
        uint32_t bB = smemU + OC_SB0 + (uint32_t)cur*OC_SB + bOff;
        int dtap = (tap/3 - 1)*34 + (tap - (tap/3)*3 - 1);
        int hrow[2];
        #pragma unroll
        for (int mi = 0; mi < 2; mi++) hrow[mi] = hrow0[mi] + dtap;

        #pragma unroll
        for (int ks = 0; ks < 4; ks++) {
            uint32_t af[2][4], bf[2][2];
            #pragma unroll
            for (int mi = 0; mi < 2; mi++) {
                int seg = ks*2 + aseg;
                uint32_t addr = hB + (uint32_t)(hrow[mi]*128
                                 + ((seg ^ (hrow[mi] & 7))*16));
                ldm_x4(af[mi][0], af[mi][1], af[mi][2], af[mi][3], addr);
            }
            ldm_x4(bf[0][0], bf[0][1], bf[1][0], bf[1][1], bB + ks*32);
            #pragma unroll
            for (int mi = 0; mi < 2; mi++)
                #pragma unroll
                for (int ni = 0; ni < 2; ni++)
                    mma16816(acc[mi][ni], af[mi], bf[ni]);
        }
        cur = nxt;
    }

    #pragma unroll
    for (int ni = 0; ni < 2; ni++) {
        int oc = nBase + ni*8 + tig*2;
        if (oc >= 18) continue;
        float b0 = bias[oc];
        float b1 = (oc + 1 < 18) ? bias[oc+1] : 0.f;
        #pragma unroll
        for (int mi = 0; mi < 2; mi++) {
            int px0 = mBase + mi*16 + grp;
            int px1 = px0 + 8;
            int y0 = tileY + (px0>>5), x0 = tileX + (px0&31);
            int y1 = tileY + (px1>>5), x1 = tileX + (px1&31);
            g_off[((size_t)(b*18 + oc)*HW) + y0*W + x0] = acc[mi][ni][0] + b0;
            g_off[((size_t)(b*18 + oc)*HW) + y1*W + x1] = acc[mi][ni][2] + b0;
            if (oc + 1 < 18) {
                g_off[((size_t)(b*18 + oc + 1)*HW) + y0*W + x0] = acc[mi][ni][1] + b1;
                g_off[((size_t)(b*18 + oc + 1)*HW) + y1*W + x1] = acc[mi][ni][3] + b1;
            }
        }
    }
}

// ---------------- kernel F: deform conv — HFMA2 blend gather (unchanged) ----------
#define D_HALO   0
#define D_SA     36864
#define D_SB     73728
#define D_SS     110592
#define D_SQ     111104
#define DEF_SMEM 111616
__global__ __launch_bounds__(256, 2) void k_deform_mma(const float* __restrict__ db) {
    extern __shared__ __align__(16) unsigned char dyn[];
    const char* halo = (const char*)(dyn + D_HALO);
    float* sS = (float*)(dyn + D_SS);
    float* sQ = (float*)(dyn + D_SQ);
    uint32_t smemU = (uint32_t)__cvta_generic_to_shared(dyn);
    uint32_t haloU = smemU + D_HALO;
    uint32_t sA_u  = smemU + D_SA;
    uint32_t sB_u  = smemU + D_SB;
    __half* sA = (__half*)(dyn + D_SA);

    int tid = threadIdx.x;
    int wid = tid >> 5, lane = tid & 31;
    int tileX = blockIdx.x * 32, tileY = blockIdx.y * 4;
    int b = blockIdx.z;
    int mBase = (wid & 1) * 64;
    int nBase = (wid >> 1) * 32;
    int grp = lane >> 2, tig = lane & 3;
    int hY0 = tileY - 2, hX0 = tileX - 2;

    uint32_t aOff = (uint32_t)(((mBase + (lane & 15))*ASTR + (lane >> 4)*8) * 2);
    uint32_t bOff = (uint32_t)(((nBase + (lane & 7) + ((lane >> 4) & 1)*8)*ASTR
                                + ((lane >> 3) & 1)*8) * 2);

    float acc[4][4][4];
    #pragma unroll
    for (int mi=0;mi<4;mi++)
        #pragma unroll
        for (int ni=0;ni<4;ni++)
            #pragma unroll
            for (int r=0;r<4;r++) acc[mi][ni][r]=0.f;

    int px_s = tid & 127;
    int half_s = tid >> 7;
    int ocb = tid >> 3, segb = tid & 7;
    int py_s = tileY + (px_s >> 5), pxg_s = tileX + (px_s & 31);

    auto haloLoad = [&](int chunk) {
        #pragma unroll
        for (int k = 0; k < 9; k++) {
            int i = tid + k*256;
            int ph = i >> 3, seg = i & 7;
            int yr = min(max(hY0 + ph/36, 0), H-1);
            int xr = min(max(hX0 + ph%36, 0), W-1);
            const __half2* src = g_hh + ((size_t)(b*HW + yr*W + xr))*NPAIR2
                                 + chunk*32 + seg*4;
            cp_async16(haloU + (uint32_t)(ph*128 + ((seg ^ (ph & 7))*16)), src);
        }
    };
    auto bLoad = [&](int it) {
        int chunk = it / 9, tap = it - chunk*9;
        const __half2* bsrc = g_wp2T + (size_t)tap*COUT*NPAIR2 + chunk*32;
        uint32_t bB = sB_u + (uint32_t)(it & 1)*18432;
        #pragma unroll
        for (int j = 0; j < 4; j++) {
            int oc = ocb + j*32;
            cp_async16(bB + (uint32_t)((oc*ASTR + segb*8) * 2),
                       bsrc + (size_t)oc*NPAIR2 + segb*4);
        }
    };

    auto gather = [&](int it, int buf) {
        int chunk = it / 9, tap = it - chunk*9;
        float dy = g_off[((size_t)(b*18 + 2*tap    )*HW) + py_s*W + pxg_s];
        float dx = g_off[((size_t)(b*18 + 2*tap + 1)*HW) + py_s*W + pxg_s];
        float py  = (float)py_s + (float)(tap/3 - 1) + dy;
        float pxx = (float)pxg_s + (float)(tap - (tap/3)*3 - 1) + dx;
        float y0f = floorf(py), x0f = floorf(pxx);
        float wy = py - y0f, wx = pxx - x0f;
        int yi = (int)y0f, xi = (int)x0f;
        bool yv0 = (yi >= 0) && (yi < H);
        bool yv1 = (yi+1 >= 0) && (yi+1 < H);
        bool xv0 = (xi >= 0) && (xi < W);
        bool xv1 = (xi+1 >= 0) && (xi+1 < W);
        float w00 = (yv0 && xv0) ? (1.f-wy)*(1.f-wx) : 0.f;
        float w01 = (yv0 && xv1) ? (1.f-wy)*wx       : 0.f;
        float w10 = (yv1 && xv0) ? wy*(1.f-wx)       : 0.f;
        float w11 = (yv1 && xv1) ? wy*wx             : 0.f;
        __half2 w00h = __float2half2_rn(w00);
        __half2 w01h = __float2half2_rn(w01);
        __half2 w10h = __float2half2_rn(w10);
        __half2 w11h = __float2half2_rn(w11);
        int ry0 = min(max(yi,   0), H-1) - hY0;
        int ry1 = min(max(yi+1, 0), H-1) - hY0;
        int rx0 = min(max(xi,   0), W-1) - hX0;
        int rx1 = min(max(xi+1, 0), W-1) - hX0;
        bool inHalo = (ry0 >= 0) && (ry1 < 8) && (rx0 >= 0) && (rx1 < 36);
        int segBase = half_s*4;
        uint32_t res[4][4];
        if (inHalo) {
            int h00 = ry0*36 + rx0, h01 = ry0*36 + rx1;
            int h10 = ry1*36 + rx0, h11 = ry1*36 + rx1;
            #pragma unroll
            for (int j = 0; j < 4; j++) {
                int seg = segBase + j;
                uint4 q0 = *(const uint4*)(halo + h00*128 + ((seg ^ (h00 & 7))*16));
                uint4 q1 = *(const uint4*)(halo + h01*128 + ((seg ^ (h01 & 7))*16));
                uint4 q2 = *(const uint4*)(halo + h10*128 + ((seg ^ (h10 & 7))*16));
                uint4 q3 = *(const uint4*)(halo + h11*128 + ((seg ^ (h11 & 7))*16));
                const uint32_t* a0 = (const uint32_t*)&q0;
                const uint32_t* a1 = (const uint32_t*)&q1;
                const uint32_t* a2 = (const uint32_t*)&q2;
                const uint32_t* a3 = (const uint32_t*)&q3;
                #pragma unroll
                for (int e = 0; e < 4; e++) {
                    __half2 v = __hmul2(*(__half2*)&a0[e], w00h);
                    v = __hfma2(*(__half2*)&a1[e], w01h, v);
                    v = __hfma2(*(__half2*)&a2[e], w10h, v);
                    v = __hfma2(*(__half2*)&a3[e], w11h, v);
                    res[j][e] = *(uint32_t*)&v;
                }
            }
        } else {
            int pb = chunk*32 + half_s*16;
            const uint4* p0 = (const uint4*)(g_hh + ((size_t)b*HW + (hY0+ry0)*W + hX0+rx0)*NPAIR2 + pb);
            const uint4* p1 = (const uint4*)(g_hh + ((size_t)b*HW + (hY0+ry0)*W + hX0+rx1)*NPAIR2 + pb);
            const uint4* p2 = (const uint4*)(g_hh + ((size_t)b*HW + (hY0+ry1)*W + hX0+rx0)*NPAIR2 + pb);
            const uint4* p3 = (const uint4*)(g_hh + ((size_t)b*HW + (hY0+ry1)*W + hX0+rx1)*NPAIR2 + pb);
            #pragma unroll
            for (int j = 0; j < 4; j++) {
                uint4 q0 = p0[j], q1 = p1[j], q2 = p2[j], q3 = p3[j];
                const uint32_t* a0 = (const uint32_t*)&q0;
                const uint32_t* a1 = (const uint32_t*)&q1;
                const uint32_t* a2 = (const uint32_t*)&q2;
                const uint32_t* a3 = (const uint32_t*)&q3;
                #pragma unroll
                for (int e = 0; e < 4; e++) {
                    __half2 v = __hmul2(*(__half2*)&a0[e], w00h);
                    v = __hfma2(*(__half2*)&a1[e], w01h, v);
                    v = __hfma2(*(__half2*)&a2[e], w10h, v);
                    v = __hfma2(*(__half2*)&a3[e], w11h, v);
                    res[j][e] = *(uint32_t*)&v;
                }
            }
        }
        __half* dst = sA + (size_t)buf*(128*ASTR) + px_s*ASTR + half_s*32;
        #pragma unroll
        for (int j = 0; j < 4; j++)
            *(uint4*)(dst + j*8) = *(uint4*)res[j];
    };

    auto mmaStep = [&](int it) {
        uint32_t aB = sA_u + (uint32_t)(it & 1)*18432 + aOff;
        uint32_t bB = sB_u + (uint32_t)(it & 1)*18432 + bOff;
        #pragma unroll
        for (int ks = 0; ks < 4; ks++) {
            uint32_t af[4][4], bf[4][2];
            #pragma unroll
            for (int mi = 0; mi < 4; mi++)
                ldm_x4(af[mi][0], af[mi][1], af[mi][2], af[mi][3],
                       aB + mi*(16*ASTR*2) + ks*32);
            ldm_x4(bf[0][0], bf[0][1], bf[1][0], bf[1][1], bB + ks*32);
            ldm_x4(bf[2][0], bf[2][1], bf[3][0], bf[3][1],
                   bB + 16*ASTR*2 + ks*32);
            #pragma unroll
            for (int mi = 0; mi < 4; mi++)
                #pragma unroll
                for (int ni = 0; ni < 4; ni++)
                    mma16816(acc[mi][ni], af[mi], bf[ni]);
        }
    };

    haloLoad(0);
    bLoad(0);
    CP_COMMIT();
    CP_WAIT0();
    __syncthreads();
    gather(0, 0);

    for (int it = 0; it < 18; it++) {
        __syncthreads();
        if (it == 8) {
            haloLoad(1);
            bLoad(9);
            CP_COMMIT();
            mmaStep(8);
            CP_WAIT0();
            continue;
        }
        if (it == 9) {
            gather(9, 1);
            bLoad(10);
            CP_COMMIT();
            gather(10, 0);
            CP_WAIT1();
            __syncthreads();
            mmaStep(9);
            continue;
        }
        if (it < 17) {
            bLoad(it+1);
            CP_COMMIT();
            if (it+1 != 9 && it+1 != 10) gather(it+1, (it+1) & 1);
            CP_WAIT1();
        } else {
            CP_WAIT0();
        }
        __syncthreads();
        mmaStep(it);
    }

    __syncthreads();
    if (tid < COUT) { sS[tid] = 0.f; sQ[tid] = 0.f; }
    __syncthreads();
    #pragma unroll
    for (int ni = 0; ni < 4; ni++) {
        int oc = nBase + ni*8 + tig*2;
        float b0 = db[oc], b1 = db[oc+1];
        float s0=0.f,q0=0.f,s1=0.f,q1=0.f;
        #pragma unroll
        for (int mi = 0; mi < 4; mi++) {
            int px0 = mBase + mi*16 + grp;
            int px1 = px0 + 8;
            size_t gp0 = ((size_t)b*HW + (tileY + (px0>>5))*W + tileX + (px0&31))*COUT;
            size_t gp1 = ((size_t)b*HW + (tileY + (px1>>5))*W + tileX + (px1&31))*COUT;
            float a0 = acc[mi][ni][0] + b0, a1 = acc[mi][ni][1] + b1;
            float a2 = acc[mi][ni][2] + b0, a3 = acc[mi][ni][3] + b1;
            *(float2*)&g_y[gp0 + oc] = make_float2(a0, a1);
            *(float2*)&g_y[gp1 + oc] = make_float2(a2, a3);
            s0 += a0 + a2; q0 += a0*a0 + a2*a2;
            s1 += a1 + a3; q1 += a1*a1 + a3*a3;
        }
        atomicAdd(&sS[oc], s0);   atomicAdd(&sQ[oc], q0);
        atomicAdd(&sS[oc+1], s1); atomicAdd(&sQ[oc+1], q1);
    }
    __syncthreads();
    if (tid < COUT) {
        atomicAdd(&g_sum2[tid], sS[tid]);
        atomicAdd(&g_sq2[tid], sQ[tid]);
    }
}

// ---------------- kernel H: fused BN2-finalize + BN2+ReLU -> planar out -----------
__global__ __launch_bounds__(256) void k_bnrelu2(const float* __restrict__ g,
                                                 const float* __restrict__ bb,
                                                 float* __restrict__ out) {
    __shared__ float s[32][129];
    __shared__ float sc[COUT], sh[COUT];
    int tid = threadIdx.x;
    if (tid < COUT) {
        float su = g_sum2[tid], q = g_sq2[tid];
        float m = su / (float)NPIX;
        float v = q / (float)NPIX - m*m;
        float scv = g[tid] * rsqrtf(v + EPSV);
        sc[tid] = scv;
        sh[tid] = bb[tid] - m * scv;
    }
    int px0 = blockIdx.x * 32;
    int b = blockIdx.y;
    #pragma unroll
    for (int j = 0; j < 16; j++) {
        int idx = tid + j*256;
        int pxl = idx >> 7, c = idx & 127;
        s[pxl][c] = g_y[((size_t)b*HW + px0 + pxl)*COUT + c];
    }
    __syncthreads();
    #pragma unroll
    for (int j = 0; j < 16; j++) {
        int idx = tid + j*256;
        int c = idx >> 5, pxl = idx & 31;
        float v = s[pxl][c] * sc[c] + sh[c];
        out[((size_t)(b*COUT + c)*HW) + px0 + pxl] = fmaxf(v, 0.f);
    }
}

// ---------------- launch -----------------------------------------------------------
extern "C" void kernel_launch(void* const* d_in, const int* in_sizes, int n_in,
                              void* d_out, int out_size) {
    const float* x       = (const float*)d_in[0];
    const float* skip    = (const float*)d_in[1];
    const float* conv1_w = (const float*)d_in[2];
    const float* bn1_g   = (const float*)d_in[3];
    const float* bn1_b   = (const float*)d_in[4];
    const float* off_w   = (const float*)d_in[5];
    const float* off_b   = (const float*)d_in[6];
    const float* def_w   = (const float*)d_in[7];
    const float* def_b   = (const float*)d_in[8];
    const float* bn2_g   = (const float*)d_in[9];
    const float* bn2_b   = (const float*)d_in[10];
    float* out = (float*)d_out;

    static bool attrDone = false;
    if (!attrDone) {
        cudaFuncSetAttribute(k_conv1_mma,
                             cudaFuncAttributeMaxDynamicSharedMemorySize, CONV1_SMEM);
        cudaFuncSetAttribute(k_offconv_mma,
                             cudaFuncAttributeMaxDynamicSharedMemorySize, OFFC_SMEM);
        cudaFuncSetAttribute(k_deform_mma,
                             cudaFuncAttributeMaxDynamicSharedMemorySize, DEF_SMEM);
        attrDone = true;
    }

    k_prep_upcat<<<NPREP_BLK + NUP_BLK, 256>>>(conv1_w, def_w, off_w, x, skip);

    k_conv1_mma<<<dim3(W/32, H/4, BATCH), 256, CONV1_SMEM>>>();

    int nhp = BATCH*HW*16;
    k_bnrelu1<<<(nhp + 255)/256, 256>>>(bn1_g, bn1_b);

    k_offconv_mma<<<dim3(W/32, H/4, BATCH), 256, OFFC_SMEM>>>(off_b);

    k_deform_mma<<<dim3(W/32, H/4, BATCH), 256, DEF_SMEM>>>(def_b);

    k_bnrelu2<<<dim3(HW/32, BATCH), 256>>>(bn2_g, bn2_b, out);
}